// round 11
// baseline (speedup 1.0000x reference)
#include <cuda_runtime.h>
#include <math.h>
#include <stdint.h>

#define Nn 20000
#define Ee 320000
#define Hh 128
#define EFK 28     // edge_attr feature count (EF + K)
#define DIN 304    // 28 + 20 + 128 + 128

// Scratch (static device globals — no runtime allocation)
__device__ float g_mi[(size_t)Nn * Hh];   // segment_sum(mij*eij)
__device__ float g_dx[(size_t)Nn * 3];    // segment_sum(rel_x*xg)

// ---------------------------------------------------------------------------
__global__ __launch_bounds__(256) void zero_kernel() {
    int i = blockIdx.x * blockDim.x + threadIdx.x;
    if (i < Nn * Hh) g_mi[i] = 0.0f;
    if (i < Nn * 3)  g_dx[i] = 0.0f;
}

// ---------------------------------------------------------------------------
__device__ __forceinline__ unsigned f2tf(float f) {
    unsigned u;
    asm("cvt.rna.tf32.f32 %0, %1;" : "=r"(u) : "f"(f));
    return u;
}

__device__ __forceinline__ void mma_tf32(float4& d,
    unsigned a0, unsigned a1, unsigned a2, unsigned a3,
    unsigned b0, unsigned b1)
{
    asm volatile(
        "mma.sync.aligned.m16n8k8.row.col.f32.tf32.tf32.f32 "
        "{%0,%1,%2,%3}, {%4,%5,%6,%7}, {%8,%9}, {%0,%1,%2,%3};\n"
        : "+f"(d.x), "+f"(d.y), "+f"(d.z), "+f"(d.w)
        : "r"(a0), "r"(a1), "r"(a2), "r"(a3), "r"(b0), "r"(b1));
}

__device__ __forceinline__ void red_add_v4(float* addr, float4 v) {
    asm volatile("red.global.add.v4.f32 [%0], {%1,%2,%3,%4};"
                 :: "l"(addr), "f"(v.x), "f"(v.y), "f"(v.z), "f"(v.w)
                 : "memory");
}

// ---------------------------------------------------------------------------
// Fused edge kernel (tensor-core tf32):
//   t1  = relu(feat @ W1 + b1)              feat = [edge_attr | rbf | h_dst | h_src]
//   mij = relu(t1 @ W2 + b2)
//   eij = sigmoid(mij @ inf_w + inf_b);  mi[dst] += mij*eij   (red.v4 atomics)
//   u   = relu(mij @ xw1 + xb1); xg = u @ xw2 + xb2; dx[dst] += rel_x*xg
// Tile: 64 edges x 128 cols, 256 threads = 8 warps (2x4 warp grid, 32x32/warp).
__global__ __launch_bounds__(256) void edge_kernel(
    const float* __restrict__ h, const float* __restrict__ x,
    const float* __restrict__ ea,
    const float* __restrict__ w1, const float* __restrict__ b1,
    const float* __restrict__ w2, const float* __restrict__ b2,
    const float* __restrict__ infw, const float* __restrict__ infb,
    const float* __restrict__ xw1, const float* __restrict__ xb1,
    const float* __restrict__ xw2, const float* __restrict__ xb2,
    const int* __restrict__ eidx)
{
    __shared__ float Ms[64][132];            // staging: tf32(t1) -> mij -> u
    __shared__ unsigned Bs[16][136];         // B tile (tf32 bits), conflict-free pad
    __shared__ int   sdst[64];
    __shared__ float srel[64][3];
    __shared__ float sl2[64];

    // As aliases the front of Ms (only live inside GEMM1 k-loop)
    unsigned (*As)[20] = reinterpret_cast<unsigned(*)[20]>(&Ms[0][0]);

    const int tid  = threadIdx.x;
    const int w    = tid >> 5;          // warp 0..7
    const int lane = tid & 31;
    const int qd   = lane >> 2;         // 0..7
    const int l4   = lane & 3;          // 0..3
    const int wm   = w >> 2;            // 0..1  (M tile of 32)
    const int wn   = w & 3;             // 0..3  (N tile of 32)
    const int R0   = wm * 32;
    const int C0   = wn * 32;
    const int ebase = blockIdx.x * 64;

    if (tid < 64) {
        int e = ebase + tid;
        int d = eidx[e], s = eidx[Ee + e];
        sdst[tid] = d;
        float rx = x[d * 3 + 0] - x[s * 3 + 0];
        float ry = x[d * 3 + 1] - x[s * 3 + 1];
        float rz = x[d * 3 + 2] - x[s * 3 + 2];
        srel[tid][0] = rx; srel[tid][1] = ry; srel[tid][2] = rz;
        sl2[tid] = sqrtf(rx * rx + ry * ry + rz * rz);
    }
    // note: h-gather indices live in registers of the filler threads only; we
    // re-read eidx inside the A-fill to avoid an extra smem array.
    __shared__ int ssrc[64];
    if (tid < 64) ssrc[tid] = eidx[Ee + ebase + tid];
    __syncthreads();

    float4 acc[2][4];
#pragma unroll
    for (int mt = 0; mt < 2; mt++)
#pragma unroll
        for (int nt = 0; nt < 4; nt++) acc[mt][nt] = make_float4(0.f, 0.f, 0.f, 0.f);

    const float delta = 100.0f / 19.0f;
    const float coeff = -0.5f / (delta * delta);

    // ---------------- GEMM1: feat(64x304) @ w1(304x128) ----------------
    for (int kt = 0; kt < 19; kt++) {
        const int k0 = kt * 16;
        __syncthreads();   // previous tile's frags consumed
        // A tile 64x16 (assembled feat, tf32)
#pragma unroll
        for (int l = 0; l < 4; l++) {
            int idx = tid + l * 256;
            int r = idx >> 4, c = idx & 15;
            int cg = k0 + c;
            float v;
            if (cg < EFK) {
                v = ea[(size_t)(ebase + r) * EFK + cg];
            } else if (cg < EFK + 20) {
                int j = cg - EFK;
                float t = sl2[r] - (float)j * delta;
                v = expf(coeff * t * t);
            } else if (cg < 48 + Hh) {
                v = h[(size_t)sdst[r] * Hh + (cg - 48)];
            } else {
                v = h[(size_t)ssrc[r] * Hh + (cg - 48 - Hh)];
            }
            As[r][c] = f2tf(v);
        }
        // B tile 16x128
#pragma unroll
        for (int l = 0; l < 8; l++) {
            int idx = tid + l * 256;
            int kr = idx >> 7, cc = idx & 127;
            Bs[kr][cc] = f2tf(w1[(size_t)(k0 + kr) * Hh + cc]);
        }
        __syncthreads();
#pragma unroll
        for (int ks = 0; ks < 16; ks += 8) {
            unsigned a[2][4], bfr[4][2];
#pragma unroll
            for (int mt = 0; mt < 2; mt++) {
                int r0 = R0 + mt * 16;
                a[mt][0] = As[r0 + qd][ks + l4];
                a[mt][1] = As[r0 + qd + 8][ks + l4];
                a[mt][2] = As[r0 + qd][ks + l4 + 4];
                a[mt][3] = As[r0 + qd + 8][ks + l4 + 4];
            }
#pragma unroll
            for (int nt = 0; nt < 4; nt++) {
                int c0 = C0 + nt * 8 + qd;
                bfr[nt][0] = Bs[ks + l4][c0];
                bfr[nt][1] = Bs[ks + l4 + 4][c0];
            }
#pragma unroll
            for (int mt = 0; mt < 2; mt++)
#pragma unroll
                for (int nt = 0; nt < 4; nt++)
                    mma_tf32(acc[mt][nt], a[mt][0], a[mt][1], a[mt][2], a[mt][3],
                             bfr[nt][0], bfr[nt][1]);
        }
    }
    __syncthreads();

    // Epilogue 1: relu(+b1), store tf32 into Ms
#pragma unroll
    for (int nt = 0; nt < 4; nt++) {
        int c = C0 + nt * 8 + 2 * l4;
        float bx = b1[c], by = b1[c + 1];
#pragma unroll
        for (int mt = 0; mt < 2; mt++) {
            int rA = R0 + mt * 16 + qd;
            Ms[rA][c]     = __uint_as_float(f2tf(fmaxf(acc[mt][nt].x + bx, 0.f)));
            Ms[rA][c + 1] = __uint_as_float(f2tf(fmaxf(acc[mt][nt].y + by, 0.f)));
            Ms[rA + 8][c]     = __uint_as_float(f2tf(fmaxf(acc[mt][nt].z + bx, 0.f)));
            Ms[rA + 8][c + 1] = __uint_as_float(f2tf(fmaxf(acc[mt][nt].w + by, 0.f)));
        }
    }
    __syncthreads();

    // ---------------- GEMM2: t1(64x128) @ w2(128x128) ----------------
#pragma unroll
    for (int mt = 0; mt < 2; mt++)
#pragma unroll
        for (int nt = 0; nt < 4; nt++) acc[mt][nt] = make_float4(0.f, 0.f, 0.f, 0.f);

    for (int kt = 0; kt < 8; kt++) {
        const int k0 = kt * 16;
        __syncthreads();
#pragma unroll
        for (int l = 0; l < 8; l++) {
            int idx = tid + l * 256;
            int kr = idx >> 7, cc = idx & 127;
            Bs[kr][cc] = f2tf(w2[(size_t)(k0 + kr) * Hh + cc]);
        }
        __syncthreads();
#pragma unroll
        for (int ks = 0; ks < 16; ks += 8) {
            unsigned a[2][4], bfr[4][2];
#pragma unroll
            for (int mt = 0; mt < 2; mt++) {
                int r0 = R0 + mt * 16;
                a[mt][0] = __float_as_uint(Ms[r0 + qd][k0 + ks + l4]);
                a[mt][1] = __float_as_uint(Ms[r0 + qd + 8][k0 + ks + l4]);
                a[mt][2] = __float_as_uint(Ms[r0 + qd][k0 + ks + l4 + 4]);
                a[mt][3] = __float_as_uint(Ms[r0 + qd + 8][k0 + ks + l4 + 4]);
            }
#pragma unroll
            for (int nt = 0; nt < 4; nt++) {
                int c0 = C0 + nt * 8 + qd;
                bfr[nt][0] = Bs[ks + l4][c0];
                bfr[nt][1] = Bs[ks + l4 + 4][c0];
            }
#pragma unroll
            for (int mt = 0; mt < 2; mt++)
#pragma unroll
                for (int nt = 0; nt < 4; nt++)
                    mma_tf32(acc[mt][nt], a[mt][0], a[mt][1], a[mt][2], a[mt][3],
                             bfr[nt][0], bfr[nt][1]);
        }
    }
    __syncthreads();   // all Ms reads done before overwrite

    // Epilogue 2: mij = relu(+b2), store fp32 into Ms
#pragma unroll
    for (int nt = 0; nt < 4; nt++) {
        int c = C0 + nt * 8 + 2 * l4;
        float bx = b2[c], by = b2[c + 1];
#pragma unroll
        for (int mt = 0; mt < 2; mt++) {
            int rA = R0 + mt * 16 + qd;
            Ms[rA][c]     = fmaxf(acc[mt][nt].x + bx, 0.f);
            Ms[rA][c + 1] = fmaxf(acc[mt][nt].y + by, 0.f);
            Ms[rA + 8][c]     = fmaxf(acc[mt][nt].z + bx, 0.f);
            Ms[rA + 8][c + 1] = fmaxf(acc[mt][nt].w + by, 0.f);
        }
    }
    __syncthreads();

    // eij + mi atomics: warp w handles rows w*8 .. w*8+7
    {
        float4 iw4 = *(const float4*)&infw[lane * 4];
        float ib = infb[0];
#pragma unroll
        for (int i = 0; i < 8; i++) {
            int r = w * 8 + i;
            float4 mv = *(const float4*)&Ms[r][lane * 4];
            float p = mv.x * iw4.x + mv.y * iw4.y + mv.z * iw4.z + mv.w * iw4.w;
#pragma unroll
            for (int off = 16; off; off >>= 1) p += __shfl_xor_sync(0xFFFFFFFFu, p, off);
            float eij = 1.0f / (1.0f + expf(-(p + ib)));
            int d = sdst[r];
            red_add_v4(&g_mi[(size_t)d * Hh + lane * 4],
                       make_float4(mv.x * eij, mv.y * eij, mv.z * eij, mv.w * eij));
        }
    }
    __syncthreads();

    // ---------------- GEMM3: mij(64x128) @ xw1(128x128) ----------------
#pragma unroll
    for (int mt = 0; mt < 2; mt++)
#pragma unroll
        for (int nt = 0; nt < 4; nt++) acc[mt][nt] = make_float4(0.f, 0.f, 0.f, 0.f);

    for (int kt = 0; kt < 8; kt++) {
        const int k0 = kt * 16;
        __syncthreads();
#pragma unroll
        for (int l = 0; l < 8; l++) {
            int idx = tid + l * 256;
            int kr = idx >> 7, cc = idx & 127;
            Bs[kr][cc] = f2tf(xw1[(size_t)(k0 + kr) * Hh + cc]);
        }
        __syncthreads();
#pragma unroll
        for (int ks = 0; ks < 16; ks += 8) {
            unsigned a[2][4], bfr[4][2];
#pragma unroll
            for (int mt = 0; mt < 2; mt++) {
                int r0 = R0 + mt * 16;
                a[mt][0] = f2tf(Ms[r0 + qd][k0 + ks + l4]);
                a[mt][1] = f2tf(Ms[r0 + qd + 8][k0 + ks + l4]);
                a[mt][2] = f2tf(Ms[r0 + qd][k0 + ks + l4 + 4]);
                a[mt][3] = f2tf(Ms[r0 + qd + 8][k0 + ks + l4 + 4]);
            }
#pragma unroll
            for (int nt = 0; nt < 4; nt++) {
                int c0 = C0 + nt * 8 + qd;
                bfr[nt][0] = Bs[ks + l4][c0];
                bfr[nt][1] = Bs[ks + l4 + 4][c0];
            }
#pragma unroll
            for (int mt = 0; mt < 2; mt++)
#pragma unroll
                for (int nt = 0; nt < 4; nt++)
                    mma_tf32(acc[mt][nt], a[mt][0], a[mt][1], a[mt][2], a[mt][3],
                             bfr[nt][0], bfr[nt][1]);
        }
    }
    __syncthreads();

    // Epilogue 3: u = relu(+xb1), store into Ms
#pragma unroll
    for (int nt = 0; nt < 4; nt++) {
        int c = C0 + nt * 8 + 2 * l4;
        float bx = xb1[c], by = xb1[c + 1];
#pragma unroll
        for (int mt = 0; mt < 2; mt++) {
            int rA = R0 + mt * 16 + qd;
            Ms[rA][c]     = fmaxf(acc[mt][nt].x + bx, 0.f);
            Ms[rA][c + 1] = fmaxf(acc[mt][nt].y + by, 0.f);
            Ms[rA + 8][c]     = fmaxf(acc[mt][nt].z + bx, 0.f);
            Ms[rA + 8][c + 1] = fmaxf(acc[mt][nt].w + by, 0.f);
        }
    }
    __syncthreads();

    // xg + dx atomics
    {
        float4 xw4 = *(const float4*)&xw2[lane * 4];
        float xb2v = xb2[0];
#pragma unroll
        for (int i = 0; i < 8; i++) {
            int r = w * 8 + i;
            float4 uv = *(const float4*)&Ms[r][lane * 4];
            float p = uv.x * xw4.x + uv.y * xw4.y + uv.z * xw4.z + uv.w * xw4.w;
#pragma unroll
            for (int off = 16; off; off >>= 1) p += __shfl_xor_sync(0xFFFFFFFFu, p, off);
            if (lane == 0) {
                float xg = p + xb2v;
                int d = sdst[r];
                atomicAdd(&g_dx[(size_t)d * 3 + 0], srel[r][0] * xg);
                atomicAdd(&g_dx[(size_t)d * 3 + 1], srel[r][1] * xg);
                atomicAdd(&g_dx[(size_t)d * 3 + 2], srel[r][2] * xg);
            }
        }
    }
}

// ---------------------------------------------------------------------------
// Node: out = relu([mi|h]@nw1+nb1)@nw2+nb2 ; x_new = x + dx/E   (fp32 FFMA)
__global__ __launch_bounds__(256) void node_kernel(
    const float* __restrict__ h, const float* __restrict__ x,
    const float* __restrict__ nw1, const float* __restrict__ nb1,
    const float* __restrict__ nw2, const float* __restrict__ nb2,
    float* __restrict__ out)
{
    __shared__ float As[64][17];
    __shared__ float Bs[16][128];
    __shared__ float Ys[64][129];

    const int tid = threadIdx.x;
    const int tx = tid & 31, ty = tid >> 5;
    const int nbase = blockIdx.x * 64;

    float acc[8][4];
#pragma unroll
    for (int i = 0; i < 8; i++)
#pragma unroll
        for (int j = 0; j < 4; j++) acc[i][j] = 0.0f;

    for (int kt = 0; kt < 16; kt++) {
        const int k0 = kt * 16;
#pragma unroll
        for (int l = 0; l < 4; l++) {
            int idx = tid + l * 256;
            int r = idx >> 4, c = idx & 15;
            int n = nbase + r, cg = k0 + c;
            float v = 0.0f;
            if (n < Nn) {
                if (cg < Hh) v = g_mi[(size_t)n * Hh + cg];
                else         v = h[(size_t)n * Hh + (cg - Hh)];
            }
            As[r][c] = v;
        }
#pragma unroll
        for (int l = 0; l < 8; l++) {
            int idx = tid + l * 256;
            int kr = idx >> 7, cc = idx & 127;
            Bs[kr][cc] = nw1[(size_t)(k0 + kr) * Hh + cc];
        }
        __syncthreads();
#pragma unroll
        for (int kk = 0; kk < 16; kk++) {
            float4 b = *(const float4*)&Bs[kk][tx * 4];
#pragma unroll
            for (int i = 0; i < 8; i++) {
                float a = As[ty + 8 * i][kk];
                acc[i][0] += a * b.x; acc[i][1] += a * b.y;
                acc[i][2] += a * b.z; acc[i][3] += a * b.w;
            }
        }
        __syncthreads();
    }

    float4 bb = *(const float4*)&nb1[tx * 4];
#pragma unroll
    for (int i = 0; i < 8; i++) {
        int r = ty + 8 * i;
        Ys[r][tx * 4 + 0] = fmaxf(acc[i][0] + bb.x, 0.0f);
        Ys[r][tx * 4 + 1] = fmaxf(acc[i][1] + bb.y, 0.0f);
        Ys[r][tx * 4 + 2] = fmaxf(acc[i][2] + bb.z, 0.0f);
        Ys[r][tx * 4 + 3] = fmaxf(acc[i][3] + bb.w, 0.0f);
    }
    __syncthreads();

    float acc2[8][4];
#pragma unroll
    for (int i = 0; i < 8; i++)
#pragma unroll
        for (int j = 0; j < 4; j++) acc2[i][j] = 0.0f;

    for (int kt = 0; kt < 8; kt++) {
        const int k0 = kt * 16;
#pragma unroll
        for (int l = 0; l < 8; l++) {
            int idx = tid + l * 256;
            int kr = idx >> 7, cc = idx & 127;
            Bs[kr][cc] = nw2[(size_t)(k0 + kr) * Hh + cc];
        }
        __syncthreads();
#pragma unroll
        for (int kk = 0; kk < 16; kk++) {
            float4 b = *(const float4*)&Bs[kk][tx * 4];
#pragma unroll
            for (int i = 0; i < 8; i++) {
                float a = Ys[ty + 8 * i][k0 + kk];
                acc2[i][0] += a * b.x; acc2[i][1] += a * b.y;
                acc2[i][2] += a * b.z; acc2[i][3] += a * b.w;
            }
        }
        __syncthreads();
    }

    float4 b2v = *(const float4*)&nb2[tx * 4];
#pragma unroll
    for (int i = 0; i < 8; i++) {
        int n = nbase + ty + 8 * i;
        if (n < Nn) {
            float4 o;
            o.x = acc2[i][0] + b2v.x;
            o.y = acc2[i][1] + b2v.y;
            o.z = acc2[i][2] + b2v.z;
            o.w = acc2[i][3] + b2v.w;
            *(float4*)&out[(size_t)n * Hh + tx * 4] = o;
        }
    }

    // x update: 64 nodes x 3 coords
    if (tid < 192) {
        int nl = tid / 3, c = tid % 3;
        int n = nbase + nl;
        if (n < Nn) {
            out[(size_t)Nn * Hh + (size_t)n * 3 + c] =
                x[(size_t)n * 3 + c] + g_dx[(size_t)n * 3 + c] * (1.0f / (float)Ee);
        }
    }
}

// ---------------------------------------------------------------------------
extern "C" void kernel_launch(void* const* d_in, const int* in_sizes, int n_in,
                              void* d_out, int out_size) {
    const float* h    = (const float*)d_in[0];
    const float* x    = (const float*)d_in[1];
    const float* ea   = (const float*)d_in[2];
    const float* ew1  = (const float*)d_in[3];
    const float* eb1  = (const float*)d_in[4];
    const float* ew2  = (const float*)d_in[5];
    const float* eb2  = (const float*)d_in[6];
    const float* infw = (const float*)d_in[7];
    const float* infb = (const float*)d_in[8];
    const float* nw1  = (const float*)d_in[9];
    const float* nb1  = (const float*)d_in[10];
    const float* nw2  = (const float*)d_in[11];
    const float* nb2  = (const float*)d_in[12];
    const float* xw1  = (const float*)d_in[13];
    const float* xb1  = (const float*)d_in[14];
    const float* xw2  = (const float*)d_in[15];
    const float* xb2  = (const float*)d_in[16];
    const int*   eidx = (const int*)d_in[17];
    float* out = (float*)d_out;

    zero_kernel<<<(Nn * Hh + 255) / 256, 256>>>();
    edge_kernel<<<Ee / 64, 256>>>(h, x, ea, ew1, eb1, ew2, eb2,
                                  infw, infb, xw1, xb1, xw2, xb2, eidx);
    node_kernel<<<(Nn + 63) / 64, 256>>>(h, x, nw1, nb1, nw2, nb2, out);
}

// round 13
// speedup vs baseline: 1.0655x; 1.0655x over previous
#include <cuda_runtime.h>
#include <math.h>
#include <stdint.h>

#define Nn 20000
#define Ee 320000
#define Hh 128
#define EFK 28     // edge_attr feature count (EF + K)
#define DIN 304    // 28 + 20 + 128 + 128

// Scratch (static device globals — no runtime allocation)
__device__ float g_mi[(size_t)Nn * Hh];   // segment_sum(mij*eij)
__device__ float g_dx[(size_t)Nn * 3];    // segment_sum(rel_x*xg)

// ---------------------------------------------------------------------------
__global__ __launch_bounds__(256) void zero_kernel() {
    int i = blockIdx.x * blockDim.x + threadIdx.x;
    if (i < Nn * Hh) g_mi[i] = 0.0f;
    if (i < Nn * 3)  g_dx[i] = 0.0f;
}

// ---------------------------------------------------------------------------
__device__ __forceinline__ unsigned f2tf(float f) {
    unsigned u;
    asm("cvt.rna.tf32.f32 %0, %1;" : "=r"(u) : "f"(f));
    return u;
}

__device__ __forceinline__ void mma_tf32(float4& d,
    unsigned a0, unsigned a1, unsigned a2, unsigned a3,
    unsigned b0, unsigned b1)
{
    asm volatile(
        "mma.sync.aligned.m16n8k8.row.col.f32.tf32.tf32.f32 "
        "{%0,%1,%2,%3}, {%4,%5,%6,%7}, {%8,%9}, {%0,%1,%2,%3};\n"
        : "+f"(d.x), "+f"(d.y), "+f"(d.z), "+f"(d.w)
        : "r"(a0), "r"(a1), "r"(a2), "r"(a3), "r"(b0), "r"(b1));
}

__device__ __forceinline__ void red_add_v4(float* addr, float4 v) {
    asm volatile("red.global.add.v4.f32 [%0], {%1,%2,%3,%4};"
                 :: "l"(addr), "f"(v.x), "f"(v.y), "f"(v.z), "f"(v.w)
                 : "memory");
}

// ---------------------------------------------------------------------------
// Fused edge kernel (tensor-core tf32):  [BYTE-IDENTICAL TO ROUND-11 PASS]
__global__ __launch_bounds__(256) void edge_kernel(
    const float* __restrict__ h, const float* __restrict__ x,
    const float* __restrict__ ea,
    const float* __restrict__ w1, const float* __restrict__ b1,
    const float* __restrict__ w2, const float* __restrict__ b2,
    const float* __restrict__ infw, const float* __restrict__ infb,
    const float* __restrict__ xw1, const float* __restrict__ xb1,
    const float* __restrict__ xw2, const float* __restrict__ xb2,
    const int* __restrict__ eidx)
{
    __shared__ float Ms[64][132];            // staging: tf32(t1) -> mij -> u
    __shared__ unsigned Bs[16][136];         // B tile (tf32 bits), conflict-free pad
    __shared__ int   sdst[64];
    __shared__ float srel[64][3];
    __shared__ float sl2[64];

    // As aliases the front of Ms (only live inside GEMM1 k-loop)
    unsigned (*As)[20] = reinterpret_cast<unsigned(*)[20]>(&Ms[0][0]);

    const int tid  = threadIdx.x;
    const int w    = tid >> 5;          // warp 0..7
    const int lane = tid & 31;
    const int qd   = lane >> 2;         // 0..7
    const int l4   = lane & 3;          // 0..3
    const int wm   = w >> 2;            // 0..1  (M tile of 32)
    const int wn   = w & 3;             // 0..3  (N tile of 32)
    const int R0   = wm * 32;
    const int C0   = wn * 32;
    const int ebase = blockIdx.x * 64;

    if (tid < 64) {
        int e = ebase + tid;
        int d = eidx[e], s = eidx[Ee + e];
        sdst[tid] = d;
        float rx = x[d * 3 + 0] - x[s * 3 + 0];
        float ry = x[d * 3 + 1] - x[s * 3 + 1];
        float rz = x[d * 3 + 2] - x[s * 3 + 2];
        srel[tid][0] = rx; srel[tid][1] = ry; srel[tid][2] = rz;
        sl2[tid] = sqrtf(rx * rx + ry * ry + rz * rz);
    }
    __shared__ int ssrc[64];
    if (tid < 64) ssrc[tid] = eidx[Ee + ebase + tid];
    __syncthreads();

    float4 acc[2][4];
#pragma unroll
    for (int mt = 0; mt < 2; mt++)
#pragma unroll
        for (int nt = 0; nt < 4; nt++) acc[mt][nt] = make_float4(0.f, 0.f, 0.f, 0.f);

    const float delta = 100.0f / 19.0f;
    const float coeff = -0.5f / (delta * delta);

    // ---------------- GEMM1: feat(64x304) @ w1(304x128) ----------------
    for (int kt = 0; kt < 19; kt++) {
        const int k0 = kt * 16;
        __syncthreads();   // previous tile's frags consumed
#pragma unroll
        for (int l = 0; l < 4; l++) {
            int idx = tid + l * 256;
            int r = idx >> 4, c = idx & 15;
            int cg = k0 + c;
            float v;
            if (cg < EFK) {
                v = ea[(size_t)(ebase + r) * EFK + cg];
            } else if (cg < EFK + 20) {
                int j = cg - EFK;
                float t = sl2[r] - (float)j * delta;
                v = expf(coeff * t * t);
            } else if (cg < 48 + Hh) {
                v = h[(size_t)sdst[r] * Hh + (cg - 48)];
            } else {
                v = h[(size_t)ssrc[r] * Hh + (cg - 48 - Hh)];
            }
            As[r][c] = f2tf(v);
        }
#pragma unroll
        for (int l = 0; l < 8; l++) {
            int idx = tid + l * 256;
            int kr = idx >> 7, cc = idx & 127;
            Bs[kr][cc] = f2tf(w1[(size_t)(k0 + kr) * Hh + cc]);
        }
        __syncthreads();
#pragma unroll
        for (int ks = 0; ks < 16; ks += 8) {
            unsigned a[2][4], bfr[4][2];
#pragma unroll
            for (int mt = 0; mt < 2; mt++) {
                int r0 = R0 + mt * 16;
                a[mt][0] = As[r0 + qd][ks + l4];
                a[mt][1] = As[r0 + qd + 8][ks + l4];
                a[mt][2] = As[r0 + qd][ks + l4 + 4];
                a[mt][3] = As[r0 + qd + 8][ks + l4 + 4];
            }
#pragma unroll
            for (int nt = 0; nt < 4; nt++) {
                int c0 = C0 + nt * 8 + qd;
                bfr[nt][0] = Bs[ks + l4][c0];
                bfr[nt][1] = Bs[ks + l4 + 4][c0];
            }
#pragma unroll
            for (int mt = 0; mt < 2; mt++)
#pragma unroll
                for (int nt = 0; nt < 4; nt++)
                    mma_tf32(acc[mt][nt], a[mt][0], a[mt][1], a[mt][2], a[mt][3],
                             bfr[nt][0], bfr[nt][1]);
        }
    }
    __syncthreads();

    // Epilogue 1: relu(+b1), store tf32 into Ms
#pragma unroll
    for (int nt = 0; nt < 4; nt++) {
        int c = C0 + nt * 8 + 2 * l4;
        float bx = b1[c], by = b1[c + 1];
#pragma unroll
        for (int mt = 0; mt < 2; mt++) {
            int rA = R0 + mt * 16 + qd;
            Ms[rA][c]     = __uint_as_float(f2tf(fmaxf(acc[mt][nt].x + bx, 0.f)));
            Ms[rA][c + 1] = __uint_as_float(f2tf(fmaxf(acc[mt][nt].y + by, 0.f)));
            Ms[rA + 8][c]     = __uint_as_float(f2tf(fmaxf(acc[mt][nt].z + bx, 0.f)));
            Ms[rA + 8][c + 1] = __uint_as_float(f2tf(fmaxf(acc[mt][nt].w + by, 0.f)));
        }
    }
    __syncthreads();

    // ---------------- GEMM2: t1(64x128) @ w2(128x128) ----------------
#pragma unroll
    for (int mt = 0; mt < 2; mt++)
#pragma unroll
        for (int nt = 0; nt < 4; nt++) acc[mt][nt] = make_float4(0.f, 0.f, 0.f, 0.f);

    for (int kt = 0; kt < 8; kt++) {
        const int k0 = kt * 16;
        __syncthreads();
#pragma unroll
        for (int l = 0; l < 8; l++) {
            int idx = tid + l * 256;
            int kr = idx >> 7, cc = idx & 127;
            Bs[kr][cc] = f2tf(w2[(size_t)(k0 + kr) * Hh + cc]);
        }
        __syncthreads();
#pragma unroll
        for (int ks = 0; ks < 16; ks += 8) {
            unsigned a[2][4], bfr[4][2];
#pragma unroll
            for (int mt = 0; mt < 2; mt++) {
                int r0 = R0 + mt * 16;
                a[mt][0] = __float_as_uint(Ms[r0 + qd][k0 + ks + l4]);
                a[mt][1] = __float_as_uint(Ms[r0 + qd + 8][k0 + ks + l4]);
                a[mt][2] = __float_as_uint(Ms[r0 + qd][k0 + ks + l4 + 4]);
                a[mt][3] = __float_as_uint(Ms[r0 + qd + 8][k0 + ks + l4 + 4]);
            }
#pragma unroll
            for (int nt = 0; nt < 4; nt++) {
                int c0 = C0 + nt * 8 + qd;
                bfr[nt][0] = Bs[ks + l4][c0];
                bfr[nt][1] = Bs[ks + l4 + 4][c0];
            }
#pragma unroll
            for (int mt = 0; mt < 2; mt++)
#pragma unroll
                for (int nt = 0; nt < 4; nt++)
                    mma_tf32(acc[mt][nt], a[mt][0], a[mt][1], a[mt][2], a[mt][3],
                             bfr[nt][0], bfr[nt][1]);
        }
    }
    __syncthreads();   // all Ms reads done before overwrite

    // Epilogue 2: mij = relu(+b2), store fp32 into Ms
#pragma unroll
    for (int nt = 0; nt < 4; nt++) {
        int c = C0 + nt * 8 + 2 * l4;
        float bx = b2[c], by = b2[c + 1];
#pragma unroll
        for (int mt = 0; mt < 2; mt++) {
            int rA = R0 + mt * 16 + qd;
            Ms[rA][c]     = fmaxf(acc[mt][nt].x + bx, 0.f);
            Ms[rA][c + 1] = fmaxf(acc[mt][nt].y + by, 0.f);
            Ms[rA + 8][c]     = fmaxf(acc[mt][nt].z + bx, 0.f);
            Ms[rA + 8][c + 1] = fmaxf(acc[mt][nt].w + by, 0.f);
        }
    }
    __syncthreads();

    // eij + mi atomics: warp w handles rows w*8 .. w*8+7
    {
        float4 iw4 = *(const float4*)&infw[lane * 4];
        float ib = infb[0];
#pragma unroll
        for (int i = 0; i < 8; i++) {
            int r = w * 8 + i;
            float4 mv = *(const float4*)&Ms[r][lane * 4];
            float p = mv.x * iw4.x + mv.y * iw4.y + mv.z * iw4.z + mv.w * iw4.w;
#pragma unroll
            for (int off = 16; off; off >>= 1) p += __shfl_xor_sync(0xFFFFFFFFu, p, off);
            float eij = 1.0f / (1.0f + expf(-(p + ib)));
            int d = sdst[r];
            red_add_v4(&g_mi[(size_t)d * Hh + lane * 4],
                       make_float4(mv.x * eij, mv.y * eij, mv.z * eij, mv.w * eij));
        }
    }
    __syncthreads();

    // ---------------- GEMM3: mij(64x128) @ xw1(128x128) ----------------
#pragma unroll
    for (int mt = 0; mt < 2; mt++)
#pragma unroll
        for (int nt = 0; nt < 4; nt++) acc[mt][nt] = make_float4(0.f, 0.f, 0.f, 0.f);

    for (int kt = 0; kt < 8; kt++) {
        const int k0 = kt * 16;
        __syncthreads();
#pragma unroll
        for (int l = 0; l < 8; l++) {
            int idx = tid + l * 256;
            int kr = idx >> 7, cc = idx & 127;
            Bs[kr][cc] = f2tf(xw1[(size_t)(k0 + kr) * Hh + cc]);
        }
        __syncthreads();
#pragma unroll
        for (int ks = 0; ks < 16; ks += 8) {
            unsigned a[2][4], bfr[4][2];
#pragma unroll
            for (int mt = 0; mt < 2; mt++) {
                int r0 = R0 + mt * 16;
                a[mt][0] = f2tf(Ms[r0 + qd][k0 + ks + l4]);
                a[mt][1] = f2tf(Ms[r0 + qd + 8][k0 + ks + l4]);
                a[mt][2] = f2tf(Ms[r0 + qd][k0 + ks + l4 + 4]);
                a[mt][3] = f2tf(Ms[r0 + qd + 8][k0 + ks + l4 + 4]);
            }
#pragma unroll
            for (int nt = 0; nt < 4; nt++) {
                int c0 = C0 + nt * 8 + qd;
                bfr[nt][0] = Bs[ks + l4][c0];
                bfr[nt][1] = Bs[ks + l4 + 4][c0];
            }
#pragma unroll
            for (int mt = 0; mt < 2; mt++)
#pragma unroll
                for (int nt = 0; nt < 4; nt++)
                    mma_tf32(acc[mt][nt], a[mt][0], a[mt][1], a[mt][2], a[mt][3],
                             bfr[nt][0], bfr[nt][1]);
        }
    }
    __syncthreads();

    // Epilogue 3: u = relu(+xb1), store into Ms
#pragma unroll
    for (int nt = 0; nt < 4; nt++) {
        int c = C0 + nt * 8 + 2 * l4;
        float bx = xb1[c], by = xb1[c + 1];
#pragma unroll
        for (int mt = 0; mt < 2; mt++) {
            int rA = R0 + mt * 16 + qd;
            Ms[rA][c]     = fmaxf(acc[mt][nt].x + bx, 0.f);
            Ms[rA][c + 1] = fmaxf(acc[mt][nt].y + by, 0.f);
            Ms[rA + 8][c]     = fmaxf(acc[mt][nt].z + bx, 0.f);
            Ms[rA + 8][c + 1] = fmaxf(acc[mt][nt].w + by, 0.f);
        }
    }
    __syncthreads();

    // xg + dx atomics
    {
        float4 xw4 = *(const float4*)&xw2[lane * 4];
        float xb2v = xb2[0];
#pragma unroll
        for (int i = 0; i < 8; i++) {
            int r = w * 8 + i;
            float4 uv = *(const float4*)&Ms[r][lane * 4];
            float p = uv.x * xw4.x + uv.y * xw4.y + uv.z * xw4.z + uv.w * xw4.w;
#pragma unroll
            for (int off = 16; off; off >>= 1) p += __shfl_xor_sync(0xFFFFFFFFu, p, off);
            if (lane == 0) {
                float xg = p + xb2v;
                int d = sdst[r];
                atomicAdd(&g_dx[(size_t)d * 3 + 0], srel[r][0] * xg);
                atomicAdd(&g_dx[(size_t)d * 3 + 1], srel[r][1] * xg);
                atomicAdd(&g_dx[(size_t)d * 3 + 2], srel[r][2] * xg);
            }
        }
    }
}

// ---------------------------------------------------------------------------
// Node (tf32 mma, static smem, in-kernel weight conversion — edge-pattern):
//   out = relu([mi|h]@nw1+nb1)@nw2+nb2 ; x_new = x + dx/E
__global__ __launch_bounds__(256) void node_kernel(
    const float* __restrict__ h, const float* __restrict__ x,
    const float* __restrict__ nw1, const float* __restrict__ nb1,
    const float* __restrict__ nw2, const float* __restrict__ nb2,
    float* __restrict__ out)
{
    __shared__ float Ms[64][132];            // staging: tf32(y)
    __shared__ unsigned Bs[16][136];

    unsigned (*As)[20] = reinterpret_cast<unsigned(*)[20]>(&Ms[0][0]);

    const int tid  = threadIdx.x;
    const int w    = tid >> 5;
    const int lane = tid & 31;
    const int qd   = lane >> 2;
    const int l4   = lane & 3;
    const int R0   = (w >> 2) * 32;
    const int C0   = (w & 3) * 32;
    const int nbase = blockIdx.x * 64;

    float4 acc[2][4];
#pragma unroll
    for (int mt = 0; mt < 2; mt++)
#pragma unroll
        for (int nt = 0; nt < 4; nt++) acc[mt][nt] = make_float4(0.f, 0.f, 0.f, 0.f);

    // ---------------- GEMM1: [mi|h](64x256) @ nw1(256x128) ----------------
    for (int kt = 0; kt < 16; kt++) {
        const int k0 = kt * 16;
        __syncthreads();
#pragma unroll
        for (int l = 0; l < 4; l++) {
            int idx = tid + l * 256;
            int r = idx >> 4, c = idx & 15;
            int n = nbase + r, cg = k0 + c;
            float v = 0.0f;
            if (n < Nn) {
                if (cg < Hh) v = g_mi[(size_t)n * Hh + cg];
                else         v = h[(size_t)n * Hh + (cg - Hh)];
            }
            As[r][c] = f2tf(v);
        }
#pragma unroll
        for (int l = 0; l < 8; l++) {
            int idx = tid + l * 256;
            int kr = idx >> 7, cc = idx & 127;
            Bs[kr][cc] = f2tf(nw1[(size_t)(k0 + kr) * Hh + cc]);
        }
        __syncthreads();
#pragma unroll
        for (int ks = 0; ks < 16; ks += 8) {
            unsigned a[2][4], bfr[4][2];
#pragma unroll
            for (int mt = 0; mt < 2; mt++) {
                int r0 = R0 + mt * 16;
                a[mt][0] = As[r0 + qd][ks + l4];
                a[mt][1] = As[r0 + qd + 8][ks + l4];
                a[mt][2] = As[r0 + qd][ks + l4 + 4];
                a[mt][3] = As[r0 + qd + 8][ks + l4 + 4];
            }
#pragma unroll
            for (int nt = 0; nt < 4; nt++) {
                int c0 = C0 + nt * 8 + qd;
                bfr[nt][0] = Bs[ks + l4][c0];
                bfr[nt][1] = Bs[ks + l4 + 4][c0];
            }
#pragma unroll
            for (int mt = 0; mt < 2; mt++)
#pragma unroll
                for (int nt = 0; nt < 4; nt++)
                    mma_tf32(acc[mt][nt], a[mt][0], a[mt][1], a[mt][2], a[mt][3],
                             bfr[nt][0], bfr[nt][1]);
        }
    }
    __syncthreads();

    // Epilogue 1: y = relu(+nb1), store tf32 bits into Ms
#pragma unroll
    for (int nt = 0; nt < 4; nt++) {
        int c = C0 + nt * 8 + 2 * l4;
        float bx = nb1[c], by = nb1[c + 1];
#pragma unroll
        for (int mt = 0; mt < 2; mt++) {
            int rA = R0 + mt * 16 + qd;
            Ms[rA][c]     = __uint_as_float(f2tf(fmaxf(acc[mt][nt].x + bx, 0.f)));
            Ms[rA][c + 1] = __uint_as_float(f2tf(fmaxf(acc[mt][nt].y + by, 0.f)));
            Ms[rA + 8][c]     = __uint_as_float(f2tf(fmaxf(acc[mt][nt].z + bx, 0.f)));
            Ms[rA + 8][c + 1] = __uint_as_float(f2tf(fmaxf(acc[mt][nt].w + by, 0.f)));
        }
    }
    __syncthreads();

    // ---------------- GEMM2: y(64x128) @ nw2(128x128) ----------------
#pragma unroll
    for (int mt = 0; mt < 2; mt++)
#pragma unroll
        for (int nt = 0; nt < 4; nt++) acc[mt][nt] = make_float4(0.f, 0.f, 0.f, 0.f);

    for (int kt = 0; kt < 8; kt++) {
        const int k0 = kt * 16;
        __syncthreads();
#pragma unroll
        for (int l = 0; l < 8; l++) {
            int idx = tid + l * 256;
            int kr = idx >> 7, cc = idx & 127;
            Bs[kr][cc] = f2tf(nw2[(size_t)(k0 + kr) * Hh + cc]);
        }
        __syncthreads();
#pragma unroll
        for (int ks = 0; ks < 16; ks += 8) {
            unsigned a[2][4], bfr[4][2];
#pragma unroll
            for (int mt = 0; mt < 2; mt++) {
                int r0 = R0 + mt * 16;
                a[mt][0] = __float_as_uint(Ms[r0 + qd][k0 + ks + l4]);
                a[mt][1] = __float_as_uint(Ms[r0 + qd + 8][k0 + ks + l4]);
                a[mt][2] = __float_as_uint(Ms[r0 + qd][k0 + ks + l4 + 4]);
                a[mt][3] = __float_as_uint(Ms[r0 + qd + 8][k0 + ks + l4 + 4]);
            }
#pragma unroll
            for (int nt = 0; nt < 4; nt++) {
                int c0 = C0 + nt * 8 + qd;
                bfr[nt][0] = Bs[ks + l4][c0];
                bfr[nt][1] = Bs[ks + l4 + 4][c0];
            }
#pragma unroll
            for (int mt = 0; mt < 2; mt++)
#pragma unroll
                for (int nt = 0; nt < 4; nt++)
                    mma_tf32(acc[mt][nt], a[mt][0], a[mt][1], a[mt][2], a[mt][3],
                             bfr[nt][0], bfr[nt][1]);
        }
    }
    __syncthreads();

    // Epilogue 2: out = acc + nb2 (guarded direct stores)
#pragma unroll
    for (int nt = 0; nt < 4; nt++) {
        int c = C0 + nt * 8 + 2 * l4;
        float bx = nb2[c], by = nb2[c + 1];
#pragma unroll
        for (int mt = 0; mt < 2; mt++) {
            int r = R0 + mt * 16 + qd;
            int n = nbase + r;
            if (n < Nn) {
                out[(size_t)n * Hh + c]     = acc[mt][nt].x + bx;
                out[(size_t)n * Hh + c + 1] = acc[mt][nt].y + by;
            }
            int n2 = n + 8;
            if (n2 < Nn) {
                out[(size_t)n2 * Hh + c]     = acc[mt][nt].z + bx;
                out[(size_t)n2 * Hh + c + 1] = acc[mt][nt].w + by;
            }
        }
    }

    // x update: 64 nodes x 3 coords
    if (tid < 192) {
        int nl = tid / 3, c = tid % 3;
        int n = nbase + nl;
        if (n < Nn) {
            out[(size_t)Nn * Hh + (size_t)n * 3 + c] =
                x[(size_t)n * 3 + c] + g_dx[(size_t)n * 3 + c] * (1.0f / (float)Ee);
        }
    }
}

// ---------------------------------------------------------------------------
extern "C" void kernel_launch(void* const* d_in, const int* in_sizes, int n_in,
                              void* d_out, int out_size) {
    const float* h    = (const float*)d_in[0];
    const float* x    = (const float*)d_in[1];
    const float* ea   = (const float*)d_in[2];
    const float* ew1  = (const float*)d_in[3];
    const float* eb1  = (const float*)d_in[4];
    const float* ew2  = (const float*)d_in[5];
    const float* eb2  = (const float*)d_in[6];
    const float* infw = (const float*)d_in[7];
    const float* infb = (const float*)d_in[8];
    const float* nw1  = (const float*)d_in[9];
    const float* nb1  = (const float*)d_in[10];
    const float* nw2  = (const float*)d_in[11];
    const float* nb2  = (const float*)d_in[12];
    const float* xw1  = (const float*)d_in[13];
    const float* xb1  = (const float*)d_in[14];
    const float* xw2  = (const float*)d_in[15];
    const float* xb2  = (const float*)d_in[16];
    const int*   eidx = (const int*)d_in[17];
    float* out = (float*)d_out;

    zero_kernel<<<(Nn * Hh + 255) / 256, 256>>>();
    edge_kernel<<<Ee / 64, 256>>>(h, x, ea, ew1, eb1, ew2, eb2,
                                  infw, infb, xw1, xb1, xw2, xb2, eidx);
    node_kernel<<<(Nn + 63) / 64, 256>>>(h, x, nw1, nb1, nw2, nb2, out);
}

// round 14
// speedup vs baseline: 1.0809x; 1.0144x over previous
#include <cuda_runtime.h>
#include <math.h>
#include <stdint.h>

#define Nn 20000
#define Ee 320000
#define Hh 128
#define EFK 28     // edge_attr feature count (EF + K)
#define DIN 304    // 28 + 20 + 128 + 128

// Scratch (static device globals — no runtime allocation)
__device__ float g_mi[(size_t)Nn * Hh];   // segment_sum(mij*eij)
__device__ float g_dx[(size_t)Nn * 3];    // segment_sum(rel_x*xg)

// ---------------------------------------------------------------------------
__global__ __launch_bounds__(256) void zero_kernel() {
    int i = blockIdx.x * blockDim.x + threadIdx.x;
    if (i < Nn * Hh) g_mi[i] = 0.0f;
    if (i < Nn * 3)  g_dx[i] = 0.0f;
}

// ---------------------------------------------------------------------------
__device__ __forceinline__ unsigned f2tf(float f) {
    unsigned u;
    asm("cvt.rna.tf32.f32 %0, %1;" : "=r"(u) : "f"(f));
    return u;
}

__device__ __forceinline__ void mma_tf32(float4& d,
    unsigned a0, unsigned a1, unsigned a2, unsigned a3,
    unsigned b0, unsigned b1)
{
    asm volatile(
        "mma.sync.aligned.m16n8k8.row.col.f32.tf32.tf32.f32 "
        "{%0,%1,%2,%3}, {%4,%5,%6,%7}, {%8,%9}, {%0,%1,%2,%3};\n"
        : "+f"(d.x), "+f"(d.y), "+f"(d.z), "+f"(d.w)
        : "r"(a0), "r"(a1), "r"(a2), "r"(a3), "r"(b0), "r"(b1));
}

__device__ __forceinline__ void red_add_v4(float* addr, float4 v) {
    asm volatile("red.global.add.v4.f32 [%0], {%1,%2,%3,%4};"
                 :: "l"(addr), "f"(v.x), "f"(v.y), "f"(v.z), "f"(v.w)
                 : "memory");
}

// B-tile register prefetch: 16 rows x 128 cols, 8 floats/thread.
// Thread (tid>>7, tid&127) covers rows {tid>>7 + 2*lb} cols {tid&127}.
#define LOADBF(reg, wsrc, k0v)                                                  \
    { _Pragma("unroll")                                                         \
      for (int lb_ = 0; lb_ < 8; lb_++)                                         \
          (reg)[lb_] = (wsrc)[(size_t)((k0v) + (tid >> 7) + 2 * lb_) * Hh + (tid & 127)]; }

#define STOREBF(reg)                                                            \
    { _Pragma("unroll")                                                         \
      for (int lb_ = 0; lb_ < 8; lb_++)                                         \
          Bs[(tid >> 7) + 2 * lb_][tid & 127] = f2tf((reg)[lb_]); }

// ---------------------------------------------------------------------------
// Fused edge kernel (tensor-core tf32, R13 skeleton + B register prefetch)
__global__ __launch_bounds__(256) void edge_kernel(
    const float* __restrict__ h, const float* __restrict__ x,
    const float* __restrict__ ea,
    const float* __restrict__ w1, const float* __restrict__ b1,
    const float* __restrict__ w2, const float* __restrict__ b2,
    const float* __restrict__ infw, const float* __restrict__ infb,
    const float* __restrict__ xw1, const float* __restrict__ xb1,
    const float* __restrict__ xw2, const float* __restrict__ xb2,
    const int* __restrict__ eidx)
{
    __shared__ float Ms[64][132];            // staging: tf32(t1) -> mij -> u
    __shared__ unsigned Bs[16][136];         // B tile (tf32 bits), conflict-free pad
    __shared__ int   sdst[64];
    __shared__ float srel[64][3];
    __shared__ float sl2[64];

    // As aliases the front of Ms (only live inside GEMM1 k-loop)
    unsigned (*As)[20] = reinterpret_cast<unsigned(*)[20]>(&Ms[0][0]);

    const int tid  = threadIdx.x;
    const int w    = tid >> 5;          // warp 0..7
    const int lane = tid & 31;
    const int qd   = lane >> 2;         // 0..7
    const int l4   = lane & 3;          // 0..3
    const int wm   = w >> 2;            // 0..1  (M tile of 32)
    const int wn   = w & 3;             // 0..3  (N tile of 32)
    const int R0   = wm * 32;
    const int C0   = wn * 32;
    const int ebase = blockIdx.x * 64;

    if (tid < 64) {
        int e = ebase + tid;
        int d = eidx[e], s = eidx[Ee + e];
        sdst[tid] = d;
        float rx = x[d * 3 + 0] - x[s * 3 + 0];
        float ry = x[d * 3 + 1] - x[s * 3 + 1];
        float rz = x[d * 3 + 2] - x[s * 3 + 2];
        srel[tid][0] = rx; srel[tid][1] = ry; srel[tid][2] = rz;
        sl2[tid] = sqrtf(rx * rx + ry * ry + rz * rz);
    }
    __shared__ int ssrc[64];
    if (tid < 64) ssrc[tid] = eidx[Ee + ebase + tid];
    __syncthreads();

    float4 acc[2][4];
#pragma unroll
    for (int mt = 0; mt < 2; mt++)
#pragma unroll
        for (int nt = 0; nt < 4; nt++) acc[mt][nt] = make_float4(0.f, 0.f, 0.f, 0.f);

    const float delta = 100.0f / 19.0f;
    const float coeff = -0.5f / (delta * delta);

    float bregs[8];

    // ---------------- GEMM1: feat(64x304) @ w1(304x128) ----------------
    LOADBF(bregs, w1, 0);

    for (int kt = 0; kt < 19; kt++) {
        const int k0 = kt * 16;
        __syncthreads();   // previous tile's frags consumed
        STOREBF(bregs);    // cvt + STS (cheap; data already in regs)
        // A tile 64x16 (assembled feat, tf32)
#pragma unroll
        for (int l = 0; l < 4; l++) {
            int idx = tid + l * 256;
            int r = idx >> 4, c = idx & 15;
            int cg = k0 + c;
            float v;
            if (cg < EFK) {
                v = ea[(size_t)(ebase + r) * EFK + cg];
            } else if (cg < EFK + 20) {
                int j = cg - EFK;
                float t = sl2[r] - (float)j * delta;
                v = expf(coeff * t * t);
            } else if (cg < 48 + Hh) {
                v = h[(size_t)sdst[r] * Hh + (cg - 48)];
            } else {
                v = h[(size_t)ssrc[r] * Hh + (cg - 48 - Hh)];
            }
            As[r][c] = f2tf(v);
        }
        if (kt < 18) { const int kn16 = (kt + 1) * 16; LOADBF(bregs, w1, kn16); }
        __syncthreads();
#pragma unroll
        for (int ks = 0; ks < 16; ks += 8) {
            unsigned a[2][4], bfr[4][2];
#pragma unroll
            for (int mt = 0; mt < 2; mt++) {
                int r0 = R0 + mt * 16;
                a[mt][0] = As[r0 + qd][ks + l4];
                a[mt][1] = As[r0 + qd + 8][ks + l4];
                a[mt][2] = As[r0 + qd][ks + l4 + 4];
                a[mt][3] = As[r0 + qd + 8][ks + l4 + 4];
            }
#pragma unroll
            for (int nt = 0; nt < 4; nt++) {
                int c0 = C0 + nt * 8 + qd;
                bfr[nt][0] = Bs[ks + l4][c0];
                bfr[nt][1] = Bs[ks + l4 + 4][c0];
            }
#pragma unroll
            for (int mt = 0; mt < 2; mt++)
#pragma unroll
                for (int nt = 0; nt < 4; nt++)
                    mma_tf32(acc[mt][nt], a[mt][0], a[mt][1], a[mt][2], a[mt][3],
                             bfr[nt][0], bfr[nt][1]);
        }
    }

    // prologue for GEMM2's first B tile (overlaps epilogue 1)
    LOADBF(bregs, w2, 0);
    __syncthreads();

    // Epilogue 1: relu(+b1), store tf32 into Ms
#pragma unroll
    for (int nt = 0; nt < 4; nt++) {
        int c = C0 + nt * 8 + 2 * l4;
        float bx = b1[c], by = b1[c + 1];
#pragma unroll
        for (int mt = 0; mt < 2; mt++) {
            int rA = R0 + mt * 16 + qd;
            Ms[rA][c]     = __uint_as_float(f2tf(fmaxf(acc[mt][nt].x + bx, 0.f)));
            Ms[rA][c + 1] = __uint_as_float(f2tf(fmaxf(acc[mt][nt].y + by, 0.f)));
            Ms[rA + 8][c]     = __uint_as_float(f2tf(fmaxf(acc[mt][nt].z + bx, 0.f)));
            Ms[rA + 8][c + 1] = __uint_as_float(f2tf(fmaxf(acc[mt][nt].w + by, 0.f)));
        }
    }
    __syncthreads();

    // ---------------- GEMM2: t1(64x128) @ w2(128x128) ----------------
#pragma unroll
    for (int mt = 0; mt < 2; mt++)
#pragma unroll
        for (int nt = 0; nt < 4; nt++) acc[mt][nt] = make_float4(0.f, 0.f, 0.f, 0.f);

    for (int kt = 0; kt < 8; kt++) {
        const int k0 = kt * 16;
        __syncthreads();
        STOREBF(bregs);
        if (kt < 7) { const int kn16 = (kt + 1) * 16; LOADBF(bregs, w2, kn16); }
        __syncthreads();
#pragma unroll
        for (int ks = 0; ks < 16; ks += 8) {
            unsigned a[2][4], bfr[4][2];
#pragma unroll
            for (int mt = 0; mt < 2; mt++) {
                int r0 = R0 + mt * 16;
                a[mt][0] = __float_as_uint(Ms[r0 + qd][k0 + ks + l4]);
                a[mt][1] = __float_as_uint(Ms[r0 + qd + 8][k0 + ks + l4]);
                a[mt][2] = __float_as_uint(Ms[r0 + qd][k0 + ks + l4 + 4]);
                a[mt][3] = __float_as_uint(Ms[r0 + qd + 8][k0 + ks + l4 + 4]);
            }
#pragma unroll
            for (int nt = 0; nt < 4; nt++) {
                int c0 = C0 + nt * 8 + qd;
                bfr[nt][0] = Bs[ks + l4][c0];
                bfr[nt][1] = Bs[ks + l4 + 4][c0];
            }
#pragma unroll
            for (int mt = 0; mt < 2; mt++)
#pragma unroll
                for (int nt = 0; nt < 4; nt++)
                    mma_tf32(acc[mt][nt], a[mt][0], a[mt][1], a[mt][2], a[mt][3],
                             bfr[nt][0], bfr[nt][1]);
        }
    }

    // prologue for GEMM3's first B tile (overlaps epilogue 2 + eij/atomics)
    LOADBF(bregs, xw1, 0);
    __syncthreads();   // all Ms reads done before overwrite

    // Epilogue 2: mij = relu(+b2), store fp32 into Ms
#pragma unroll
    for (int nt = 0; nt < 4; nt++) {
        int c = C0 + nt * 8 + 2 * l4;
        float bx = b2[c], by = b2[c + 1];
#pragma unroll
        for (int mt = 0; mt < 2; mt++) {
            int rA = R0 + mt * 16 + qd;
            Ms[rA][c]     = fmaxf(acc[mt][nt].x + bx, 0.f);
            Ms[rA][c + 1] = fmaxf(acc[mt][nt].y + by, 0.f);
            Ms[rA + 8][c]     = fmaxf(acc[mt][nt].z + bx, 0.f);
            Ms[rA + 8][c + 1] = fmaxf(acc[mt][nt].w + by, 0.f);
        }
    }
    __syncthreads();

    // eij + mi atomics: warp w handles rows w*8 .. w*8+7
    {
        float4 iw4 = *(const float4*)&infw[lane * 4];
        float ib = infb[0];
#pragma unroll
        for (int i = 0; i < 8; i++) {
            int r = w * 8 + i;
            float4 mv = *(const float4*)&Ms[r][lane * 4];
            float p = mv.x * iw4.x + mv.y * iw4.y + mv.z * iw4.z + mv.w * iw4.w;
#pragma unroll
            for (int off = 16; off; off >>= 1) p += __shfl_xor_sync(0xFFFFFFFFu, p, off);
            float eij = 1.0f / (1.0f + expf(-(p + ib)));
            int d = sdst[r];
            red_add_v4(&g_mi[(size_t)d * Hh + lane * 4],
                       make_float4(mv.x * eij, mv.y * eij, mv.z * eij, mv.w * eij));
        }
    }
    __syncthreads();

    // ---------------- GEMM3: mij(64x128) @ xw1(128x128) ----------------
#pragma unroll
    for (int mt = 0; mt < 2; mt++)
#pragma unroll
        for (int nt = 0; nt < 4; nt++) acc[mt][nt] = make_float4(0.f, 0.f, 0.f, 0.f);

    for (int kt = 0; kt < 8; kt++) {
        const int k0 = kt * 16;
        __syncthreads();
        STOREBF(bregs);
        if (kt < 7) { const int kn16 = (kt + 1) * 16; LOADBF(bregs, xw1, kn16); }
        __syncthreads();
#pragma unroll
        for (int ks = 0; ks < 16; ks += 8) {
            unsigned a[2][4], bfr[4][2];
#pragma unroll
            for (int mt = 0; mt < 2; mt++) {
                int r0 = R0 + mt * 16;
                a[mt][0] = f2tf(Ms[r0 + qd][k0 + ks + l4]);
                a[mt][1] = f2tf(Ms[r0 + qd + 8][k0 + ks + l4]);
                a[mt][2] = f2tf(Ms[r0 + qd][k0 + ks + l4 + 4]);
                a[mt][3] = f2tf(Ms[r0 + qd + 8][k0 + ks + l4 + 4]);
            }
#pragma unroll
            for (int nt = 0; nt < 4; nt++) {
                int c0 = C0 + nt * 8 + qd;
                bfr[nt][0] = Bs[ks + l4][c0];
                bfr[nt][1] = Bs[ks + l4 + 4][c0];
            }
#pragma unroll
            for (int mt = 0; mt < 2; mt++)
#pragma unroll
                for (int nt = 0; nt < 4; nt++)
                    mma_tf32(acc[mt][nt], a[mt][0], a[mt][1], a[mt][2], a[mt][3],
                             bfr[nt][0], bfr[nt][1]);
        }
    }
    __syncthreads();

    // Epilogue 3: u = relu(+xb1), store into Ms
#pragma unroll
    for (int nt = 0; nt < 4; nt++) {
        int c = C0 + nt * 8 + 2 * l4;
        float bx = xb1[c], by = xb1[c + 1];
#pragma unroll
        for (int mt = 0; mt < 2; mt++) {
            int rA = R0 + mt * 16 + qd;
            Ms[rA][c]     = fmaxf(acc[mt][nt].x + bx, 0.f);
            Ms[rA][c + 1] = fmaxf(acc[mt][nt].y + by, 0.f);
            Ms[rA + 8][c]     = fmaxf(acc[mt][nt].z + bx, 0.f);
            Ms[rA + 8][c + 1] = fmaxf(acc[mt][nt].w + by, 0.f);
        }
    }
    __syncthreads();

    // xg + dx atomics
    {
        float4 xw4 = *(const float4*)&xw2[lane * 4];
        float xb2v = xb2[0];
#pragma unroll
        for (int i = 0; i < 8; i++) {
            int r = w * 8 + i;
            float4 uv = *(const float4*)&Ms[r][lane * 4];
            float p = uv.x * xw4.x + uv.y * xw4.y + uv.z * xw4.z + uv.w * xw4.w;
#pragma unroll
            for (int off = 16; off; off >>= 1) p += __shfl_xor_sync(0xFFFFFFFFu, p, off);
            if (lane == 0) {
                float xg = p + xb2v;
                int d = sdst[r];
                atomicAdd(&g_dx[(size_t)d * 3 + 0], srel[r][0] * xg);
                atomicAdd(&g_dx[(size_t)d * 3 + 1], srel[r][1] * xg);
                atomicAdd(&g_dx[(size_t)d * 3 + 2], srel[r][2] * xg);
            }
        }
    }
}

// ---------------------------------------------------------------------------
// Node (tf32 mma, static smem, R13 structure + B register prefetch):
//   out = relu([mi|h]@nw1+nb1)@nw2+nb2 ; x_new = x + dx/E
__global__ __launch_bounds__(256) void node_kernel(
    const float* __restrict__ h, const float* __restrict__ x,
    const float* __restrict__ nw1, const float* __restrict__ nb1,
    const float* __restrict__ nw2, const float* __restrict__ nb2,
    float* __restrict__ out)
{
    __shared__ float Ms[64][132];            // staging: tf32(y)
    __shared__ unsigned Bs[16][136];

    unsigned (*As)[20] = reinterpret_cast<unsigned(*)[20]>(&Ms[0][0]);

    const int tid  = threadIdx.x;
    const int w    = tid >> 5;
    const int lane = tid & 31;
    const int qd   = lane >> 2;
    const int l4   = lane & 3;
    const int R0   = (w >> 2) * 32;
    const int C0   = (w & 3) * 32;
    const int nbase = blockIdx.x * 64;

    float4 acc[2][4];
#pragma unroll
    for (int mt = 0; mt < 2; mt++)
#pragma unroll
        for (int nt = 0; nt < 4; nt++) acc[mt][nt] = make_float4(0.f, 0.f, 0.f, 0.f);

    float bregs[8];

    // ---------------- GEMM1: [mi|h](64x256) @ nw1(256x128) ----------------
    LOADBF(bregs, nw1, 0);

    for (int kt = 0; kt < 16; kt++) {
        const int k0 = kt * 16;
        __syncthreads();
        STOREBF(bregs);
#pragma unroll
        for (int l = 0; l < 4; l++) {
            int idx = tid + l * 256;
            int r = idx >> 4, c = idx & 15;
            int n = nbase + r, cg = k0 + c;
            float v = 0.0f;
            if (n < Nn) {
                if (cg < Hh) v = g_mi[(size_t)n * Hh + cg];
                else         v = h[(size_t)n * Hh + (cg - Hh)];
            }
            As[r][c] = f2tf(v);
        }
        if (kt < 15) { const int kn16 = (kt + 1) * 16; LOADBF(bregs, nw1, kn16); }
        __syncthreads();
#pragma unroll
        for (int ks = 0; ks < 16; ks += 8) {
            unsigned a[2][4], bfr[4][2];
#pragma unroll
            for (int mt = 0; mt < 2; mt++) {
                int r0 = R0 + mt * 16;
                a[mt][0] = As[r0 + qd][ks + l4];
                a[mt][1] = As[r0 + qd + 8][ks + l4];
                a[mt][2] = As[r0 + qd][ks + l4 + 4];
                a[mt][3] = As[r0 + qd + 8][ks + l4 + 4];
            }
#pragma unroll
            for (int nt = 0; nt < 4; nt++) {
                int c0 = C0 + nt * 8 + qd;
                bfr[nt][0] = Bs[ks + l4][c0];
                bfr[nt][1] = Bs[ks + l4 + 4][c0];
            }
#pragma unroll
            for (int mt = 0; mt < 2; mt++)
#pragma unroll
                for (int nt = 0; nt < 4; nt++)
                    mma_tf32(acc[mt][nt], a[mt][0], a[mt][1], a[mt][2], a[mt][3],
                             bfr[nt][0], bfr[nt][1]);
        }
    }

    // prologue for GEMM2's first B tile (overlaps epilogue 1)
    LOADBF(bregs, nw2, 0);
    __syncthreads();

    // Epilogue 1: y = relu(+nb1), store tf32 bits into Ms
#pragma unroll
    for (int nt = 0; nt < 4; nt++) {
        int c = C0 + nt * 8 + 2 * l4;
        float bx = nb1[c], by = nb1[c + 1];
#pragma unroll
        for (int mt = 0; mt < 2; mt++) {
            int rA = R0 + mt * 16 + qd;
            Ms[rA][c]     = __uint_as_float(f2tf(fmaxf(acc[mt][nt].x + bx, 0.f)));
            Ms[rA][c + 1] = __uint_as_float(f2tf(fmaxf(acc[mt][nt].y + by, 0.f)));
            Ms[rA + 8][c]     = __uint_as_float(f2tf(fmaxf(acc[mt][nt].z + bx, 0.f)));
            Ms[rA + 8][c + 1] = __uint_as_float(f2tf(fmaxf(acc[mt][nt].w + by, 0.f)));
        }
    }
    __syncthreads();

    // ---------------- GEMM2: y(64x128) @ nw2(128x128) ----------------
#pragma unroll
    for (int mt = 0; mt < 2; mt++)
#pragma unroll
        for (int nt = 0; nt < 4; nt++) acc[mt][nt] = make_float4(0.f, 0.f, 0.f, 0.f);

    for (int kt = 0; kt < 8; kt++) {
        const int k0 = kt * 16;
        __syncthreads();
        STOREBF(bregs);
        if (kt < 7) { const int kn16 = (kt + 1) * 16; LOADBF(bregs, nw2, kn16); }
        __syncthreads();
#pragma unroll
        for (int ks = 0; ks < 16; ks += 8) {
            unsigned a[2][4], bfr[4][2];
#pragma unroll
            for (int mt = 0; mt < 2; mt++) {
                int r0 = R0 + mt * 16;
                a[mt][0] = __float_as_uint(Ms[r0 + qd][k0 + ks + l4]);
                a[mt][1] = __float_as_uint(Ms[r0 + qd + 8][k0 + ks + l4]);
                a[mt][2] = __float_as_uint(Ms[r0 + qd][k0 + ks + l4 + 4]);
                a[mt][3] = __float_as_uint(Ms[r0 + qd + 8][k0 + ks + l4 + 4]);
            }
#pragma unroll
            for (int nt = 0; nt < 4; nt++) {
                int c0 = C0 + nt * 8 + qd;
                bfr[nt][0] = Bs[ks + l4][c0];
                bfr[nt][1] = Bs[ks + l4 + 4][c0];
            }
#pragma unroll
            for (int mt = 0; mt < 2; mt++)
#pragma unroll
                for (int nt = 0; nt < 4; nt++)
                    mma_tf32(acc[mt][nt], a[mt][0], a[mt][1], a[mt][2], a[mt][3],
                             bfr[nt][0], bfr[nt][1]);
        }
    }
    __syncthreads();

    // Epilogue 2: out = acc + nb2 (guarded direct stores)
#pragma unroll
    for (int nt = 0; nt < 4; nt++) {
        int c = C0 + nt * 8 + 2 * l4;
        float bx = nb2[c], by = nb2[c + 1];
#pragma unroll
        for (int mt = 0; mt < 2; mt++) {
            int r = R0 + mt * 16 + qd;
            int n = nbase + r;
            if (n < Nn) {
                out[(size_t)n * Hh + c]     = acc[mt][nt].x + bx;
                out[(size_t)n * Hh + c + 1] = acc[mt][nt].y + by;
            }
            int n2 = n + 8;
            if (n2 < Nn) {
                out[(size_t)n2 * Hh + c]     = acc[mt][nt].z + bx;
                out[(size_t)n2 * Hh + c + 1] = acc[mt][nt].w + by;
            }
        }
    }

    // x update: 64 nodes x 3 coords
    if (tid < 192) {
        int nl = tid / 3, c = tid % 3;
        int n = nbase + nl;
        if (n < Nn) {
            out[(size_t)Nn * Hh + (size_t)n * 3 + c] =
                x[(size_t)n * 3 + c] + g_dx[(size_t)n * 3 + c] * (1.0f / (float)Ee);
        }
    }
}

// ---------------------------------------------------------------------------
extern "C" void kernel_launch(void* const* d_in, const int* in_sizes, int n_in,
                              void* d_out, int out_size) {
    const float* h    = (const float*)d_in[0];
    const float* x    = (const float*)d_in[1];
    const float* ea   = (const float*)d_in[2];
    const float* ew1  = (const float*)d_in[3];
    const float* eb1  = (const float*)d_in[4];
    const float* ew2  = (const float*)d_in[5];
    const float* eb2  = (const float*)d_in[6];
    const float* infw = (const float*)d_in[7];
    const float* infb = (const float*)d_in[8];
    const float* nw1  = (const float*)d_in[9];
    const float* nb1  = (const float*)d_in[10];
    const float* nw2  = (const float*)d_in[11];
    const float* nb2  = (const float*)d_in[12];
    const float* xw1  = (const float*)d_in[13];
    const float* xb1  = (const float*)d_in[14];
    const float* xw2  = (const float*)d_in[15];
    const float* xb2  = (const float*)d_in[16];
    const int*   eidx = (const int*)d_in[17];
    float* out = (float*)d_out;

    zero_kernel<<<(Nn * Hh + 255) / 256, 256>>>();
    edge_kernel<<<Ee / 64, 256>>>(h, x, ea, ew1, eb1, ew2, eb2,
                                  infw, infb, xw1, xb1, xw2, xb2, eidx);
    node_kernel<<<(Nn + 63) / 64, 256>>>(h, x, nw1, nb1, nw2, nb2, out);
}

// round 15
// speedup vs baseline: 1.3505x; 1.2495x over previous
#include <cuda_runtime.h>
#include <math.h>
#include <stdint.h>

#define Nn 20000
#define Ee 320000
#define Hh 128
#define EFK 28     // edge_attr feature count (EF + K)
#define DIN 304    // 28 + 20 + 128 + 128

// Scratch (static device globals — no runtime allocation)
__device__ float g_mi[(size_t)Nn * Hh];   // segment_sum(mij*eij)
__device__ float g_dx[(size_t)Nn * 3];    // segment_sum(rel_x*xg)

// ---------------------------------------------------------------------------
__global__ __launch_bounds__(256) void zero_kernel() {
    int i = blockIdx.x * blockDim.x + threadIdx.x;
    if (i < Nn * Hh) g_mi[i] = 0.0f;
    if (i < Nn * 3)  g_dx[i] = 0.0f;
}

// ---------------------------------------------------------------------------
__device__ __forceinline__ unsigned f2tf(float f) {
    unsigned u;
    asm("cvt.rna.tf32.f32 %0, %1;" : "=r"(u) : "f"(f));
    return u;
}

__device__ __forceinline__ void mma_tf32(float4& d,
    unsigned a0, unsigned a1, unsigned a2, unsigned a3,
    unsigned b0, unsigned b1)
{
    asm volatile(
        "mma.sync.aligned.m16n8k8.row.col.f32.tf32.tf32.f32 "
        "{%0,%1,%2,%3}, {%4,%5,%6,%7}, {%8,%9}, {%0,%1,%2,%3};\n"
        : "+f"(d.x), "+f"(d.y), "+f"(d.z), "+f"(d.w)
        : "r"(a0), "r"(a1), "r"(a2), "r"(a3), "r"(b0), "r"(b1));
}

__device__ __forceinline__ void red_add_v4(float* addr, float4 v) {
    asm volatile("red.global.add.v4.f32 [%0], {%1,%2,%3,%4};"
                 :: "l"(addr), "f"(v.x), "f"(v.y), "f"(v.z), "f"(v.w)
                 : "memory");
}

// B-tile register prefetch: 16 rows x 128 cols, 8 floats/thread.
#define LOADBF(reg, wsrc, k0v)                                                  \
    { _Pragma("unroll")                                                         \
      for (int lb_ = 0; lb_ < 8; lb_++)                                         \
          (reg)[lb_] = (wsrc)[(size_t)((k0v) + (tid >> 7) + 2 * lb_) * Hh + (tid & 127)]; }

#define STOREBF(reg)                                                            \
    { _Pragma("unroll")                                                         \
      for (int lb_ = 0; lb_ < 8; lb_++)                                         \
          Bs[(tid >> 7) + 2 * lb_][tid & 127] = f2tf((reg)[lb_]); }

// ---------------------------------------------------------------------------
// Fused edge kernel (tf32 mma, R14 skeleton + A-side h-gather prefetch)
__global__ __launch_bounds__(256) void edge_kernel(
    const float* __restrict__ h, const float* __restrict__ x,
    const float* __restrict__ ea,
    const float* __restrict__ w1, const float* __restrict__ b1,
    const float* __restrict__ w2, const float* __restrict__ b2,
    const float* __restrict__ infw, const float* __restrict__ infb,
    const float* __restrict__ xw1, const float* __restrict__ xb1,
    const float* __restrict__ xw2, const float* __restrict__ xb2,
    const int* __restrict__ eidx)
{
    __shared__ float Ms[64][132];            // staging: tf32(t1) -> mij -> u
    __shared__ unsigned Bs[16][136];         // B tile (tf32 bits), conflict-free pad
    __shared__ int   sdst[64];
    __shared__ float srel[64][3];
    __shared__ float sl2[64];

    // As aliases the front of Ms (only live inside GEMM1 k-loop)
    unsigned (*As)[20] = reinterpret_cast<unsigned(*)[20]>(&Ms[0][0]);

    const int tid  = threadIdx.x;
    const int w    = tid >> 5;          // warp 0..7
    const int lane = tid & 31;
    const int qd   = lane >> 2;         // 0..7
    const int l4   = lane & 3;          // 0..3
    const int wm   = w >> 2;            // 0..1  (M tile of 32)
    const int wn   = w & 3;             // 0..3  (N tile of 32)
    const int R0   = wm * 32;
    const int C0   = wn * 32;
    const int ebase = blockIdx.x * 64;

    if (tid < 64) {
        int e = ebase + tid;
        int d = eidx[e], s = eidx[Ee + e];
        sdst[tid] = d;
        float rx = x[d * 3 + 0] - x[s * 3 + 0];
        float ry = x[d * 3 + 1] - x[s * 3 + 1];
        float rz = x[d * 3 + 2] - x[s * 3 + 2];
        srel[tid][0] = rx; srel[tid][1] = ry; srel[tid][2] = rz;
        sl2[tid] = sqrtf(rx * rx + ry * ry + rz * rz);
    }
    __shared__ int ssrc[64];
    if (tid < 64) ssrc[tid] = eidx[Ee + ebase + tid];
    __syncthreads();

    float4 acc[2][4];
#pragma unroll
    for (int mt = 0; mt < 2; mt++)
#pragma unroll
        for (int nt = 0; nt < 4; nt++) acc[mt][nt] = make_float4(0.f, 0.f, 0.f, 0.f);

    const float delta = 100.0f / 19.0f;
    const float coeff = -0.5f / (delta * delta);

    float bregs[8];
    float4 ha = make_float4(0.f, 0.f, 0.f, 0.f);   // A-side h prefetch
    const int ar  = tid >> 2;                      // 0..63 (A row)
    const int ac4 = (tid & 3) * 4;                 // col group

    // ---------------- GEMM1: feat(64x304) @ w1(304x128) ----------------
    LOADBF(bregs, w1, 0);

    for (int kt = 0; kt < 19; kt++) {
        const int k0 = kt * 16;
        __syncthreads();   // previous tile's frags consumed
        STOREBF(bregs);    // cvt + STS (data already in regs)
        if (kt < 3) {
            // scalar fill: tiles 0..2 cover cg 0..47 (edge_attr + rbf only)
#pragma unroll
            for (int l = 0; l < 4; l++) {
                int idx = tid + l * 256;
                int r = idx >> 4, c = idx & 15;
                int cg = k0 + c;
                float v;
                if (cg < EFK) {
                    v = ea[(size_t)(ebase + r) * EFK + cg];
                } else {
                    int j = cg - EFK;
                    float t = sl2[r] - (float)j * delta;
                    v = expf(coeff * t * t);
                }
                As[r][c] = f2tf(v);
            }
        } else {
            // prefetched h tile: cvt + scalar STS only
            As[ar][ac4 + 0] = f2tf(ha.x);
            As[ar][ac4 + 1] = f2tf(ha.y);
            As[ar][ac4 + 2] = f2tf(ha.z);
            As[ar][ac4 + 3] = f2tf(ha.w);
        }
        if (kt < 18) {
            const int kn = kt + 1;
            LOADBF(bregs, w1, kn * 16);
            if (kn >= 3) {
                const int* ridx = (kn < 11) ? sdst : ssrc;
                const int hb = ((kn - 3) & 7) * 16;
                ha = *(const float4*)&h[(size_t)ridx[ar] * Hh + hb + ac4];
            }
        }
        __syncthreads();
#pragma unroll
        for (int ks = 0; ks < 16; ks += 8) {
            unsigned a[2][4], bfr[4][2];
#pragma unroll
            for (int mt = 0; mt < 2; mt++) {
                int r0 = R0 + mt * 16;
                a[mt][0] = As[r0 + qd][ks + l4];
                a[mt][1] = As[r0 + qd + 8][ks + l4];
                a[mt][2] = As[r0 + qd][ks + l4 + 4];
                a[mt][3] = As[r0 + qd + 8][ks + l4 + 4];
            }
#pragma unroll
            for (int nt = 0; nt < 4; nt++) {
                int c0 = C0 + nt * 8 + qd;
                bfr[nt][0] = Bs[ks + l4][c0];
                bfr[nt][1] = Bs[ks + l4 + 4][c0];
            }
#pragma unroll
            for (int mt = 0; mt < 2; mt++)
#pragma unroll
                for (int nt = 0; nt < 4; nt++)
                    mma_tf32(acc[mt][nt], a[mt][0], a[mt][1], a[mt][2], a[mt][3],
                             bfr[nt][0], bfr[nt][1]);
        }
    }

    // prologue for GEMM2's first B tile (overlaps epilogue 1)
    LOADBF(bregs, w2, 0);
    __syncthreads();

    // Epilogue 1: relu(+b1), store tf32 into Ms
#pragma unroll
    for (int nt = 0; nt < 4; nt++) {
        int c = C0 + nt * 8 + 2 * l4;
        float bx = b1[c], by = b1[c + 1];
#pragma unroll
        for (int mt = 0; mt < 2; mt++) {
            int rA = R0 + mt * 16 + qd;
            Ms[rA][c]     = __uint_as_float(f2tf(fmaxf(acc[mt][nt].x + bx, 0.f)));
            Ms[rA][c + 1] = __uint_as_float(f2tf(fmaxf(acc[mt][nt].y + by, 0.f)));
            Ms[rA + 8][c]     = __uint_as_float(f2tf(fmaxf(acc[mt][nt].z + bx, 0.f)));
            Ms[rA + 8][c + 1] = __uint_as_float(f2tf(fmaxf(acc[mt][nt].w + by, 0.f)));
        }
    }
    __syncthreads();

    // ---------------- GEMM2: t1(64x128) @ w2(128x128) ----------------
#pragma unroll
    for (int mt = 0; mt < 2; mt++)
#pragma unroll
        for (int nt = 0; nt < 4; nt++) acc[mt][nt] = make_float4(0.f, 0.f, 0.f, 0.f);

    for (int kt = 0; kt < 8; kt++) {
        const int k0 = kt * 16;
        __syncthreads();
        STOREBF(bregs);
        if (kt < 7) { const int kn16 = (kt + 1) * 16; LOADBF(bregs, w2, kn16); }
        __syncthreads();
#pragma unroll
        for (int ks = 0; ks < 16; ks += 8) {
            unsigned a[2][4], bfr[4][2];
#pragma unroll
            for (int mt = 0; mt < 2; mt++) {
                int r0 = R0 + mt * 16;
                a[mt][0] = __float_as_uint(Ms[r0 + qd][k0 + ks + l4]);
                a[mt][1] = __float_as_uint(Ms[r0 + qd + 8][k0 + ks + l4]);
                a[mt][2] = __float_as_uint(Ms[r0 + qd][k0 + ks + l4 + 4]);
                a[mt][3] = __float_as_uint(Ms[r0 + qd + 8][k0 + ks + l4 + 4]);
            }
#pragma unroll
            for (int nt = 0; nt < 4; nt++) {
                int c0 = C0 + nt * 8 + qd;
                bfr[nt][0] = Bs[ks + l4][c0];
                bfr[nt][1] = Bs[ks + l4 + 4][c0];
            }
#pragma unroll
            for (int mt = 0; mt < 2; mt++)
#pragma unroll
                for (int nt = 0; nt < 4; nt++)
                    mma_tf32(acc[mt][nt], a[mt][0], a[mt][1], a[mt][2], a[mt][3],
                             bfr[nt][0], bfr[nt][1]);
        }
    }

    // prologue for GEMM3's first B tile (overlaps epilogue 2 + eij/atomics)
    LOADBF(bregs, xw1, 0);
    __syncthreads();   // all Ms reads done before overwrite

    // Epilogue 2: mij = relu(+b2), store fp32 into Ms
#pragma unroll
    for (int nt = 0; nt < 4; nt++) {
        int c = C0 + nt * 8 + 2 * l4;
        float bx = b2[c], by = b2[c + 1];
#pragma unroll
        for (int mt = 0; mt < 2; mt++) {
            int rA = R0 + mt * 16 + qd;
            Ms[rA][c]     = fmaxf(acc[mt][nt].x + bx, 0.f);
            Ms[rA][c + 1] = fmaxf(acc[mt][nt].y + by, 0.f);
            Ms[rA + 8][c]     = fmaxf(acc[mt][nt].z + bx, 0.f);
            Ms[rA + 8][c + 1] = fmaxf(acc[mt][nt].w + by, 0.f);
        }
    }
    __syncthreads();

    // eij + mi atomics: warp w handles rows w*8 .. w*8+7
    {
        float4 iw4 = *(const float4*)&infw[lane * 4];
        float ib = infb[0];
#pragma unroll
        for (int i = 0; i < 8; i++) {
            int r = w * 8 + i;
            float4 mv = *(const float4*)&Ms[r][lane * 4];
            float p = mv.x * iw4.x + mv.y * iw4.y + mv.z * iw4.z + mv.w * iw4.w;
#pragma unroll
            for (int off = 16; off; off >>= 1) p += __shfl_xor_sync(0xFFFFFFFFu, p, off);
            float eij = 1.0f / (1.0f + expf(-(p + ib)));
            int d = sdst[r];
            red_add_v4(&g_mi[(size_t)d * Hh + lane * 4],
                       make_float4(mv.x * eij, mv.y * eij, mv.z * eij, mv.w * eij));
        }
    }
    __syncthreads();

    // ---------------- GEMM3: mij(64x128) @ xw1(128x128) ----------------
#pragma unroll
    for (int mt = 0; mt < 2; mt++)
#pragma unroll
        for (int nt = 0; nt < 4; nt++) acc[mt][nt] = make_float4(0.f, 0.f, 0.f, 0.f);

    for (int kt = 0; kt < 8; kt++) {
        const int k0 = kt * 16;
        __syncthreads();
        STOREBF(bregs);
        if (kt < 7) { const int kn16 = (kt + 1) * 16; LOADBF(bregs, xw1, kn16); }
        __syncthreads();
#pragma unroll
        for (int ks = 0; ks < 16; ks += 8) {
            unsigned a[2][4], bfr[4][2];
#pragma unroll
            for (int mt = 0; mt < 2; mt++) {
                int r0 = R0 + mt * 16;
                a[mt][0] = f2tf(Ms[r0 + qd][k0 + ks + l4]);
                a[mt][1] = f2tf(Ms[r0 + qd + 8][k0 + ks + l4]);
                a[mt][2] = f2tf(Ms[r0 + qd][k0 + ks + l4 + 4]);
                a[mt][3] = f2tf(Ms[r0 + qd + 8][k0 + ks + l4 + 4]);
            }
#pragma unroll
            for (int nt = 0; nt < 4; nt++) {
                int c0 = C0 + nt * 8 + qd;
                bfr[nt][0] = Bs[ks + l4][c0];
                bfr[nt][1] = Bs[ks + l4 + 4][c0];
            }
#pragma unroll
            for (int mt = 0; mt < 2; mt++)
#pragma unroll
                for (int nt = 0; nt < 4; nt++)
                    mma_tf32(acc[mt][nt], a[mt][0], a[mt][1], a[mt][2], a[mt][3],
                             bfr[nt][0], bfr[nt][1]);
        }
    }
    __syncthreads();

    // Epilogue 3: u = relu(+xb1), store into Ms
#pragma unroll
    for (int nt = 0; nt < 4; nt++) {
        int c = C0 + nt * 8 + 2 * l4;
        float bx = xb1[c], by = xb1[c + 1];
#pragma unroll
        for (int mt = 0; mt < 2; mt++) {
            int rA = R0 + mt * 16 + qd;
            Ms[rA][c]     = fmaxf(acc[mt][nt].x + bx, 0.f);
            Ms[rA][c + 1] = fmaxf(acc[mt][nt].y + by, 0.f);
            Ms[rA + 8][c]     = fmaxf(acc[mt][nt].z + bx, 0.f);
            Ms[rA + 8][c + 1] = fmaxf(acc[mt][nt].w + by, 0.f);
        }
    }
    __syncthreads();

    // xg + dx atomics
    {
        float4 xw4 = *(const float4*)&xw2[lane * 4];
        float xb2v = xb2[0];
#pragma unroll
        for (int i = 0; i < 8; i++) {
            int r = w * 8 + i;
            float4 uv = *(const float4*)&Ms[r][lane * 4];
            float p = uv.x * xw4.x + uv.y * xw4.y + uv.z * xw4.z + uv.w * xw4.w;
#pragma unroll
            for (int off = 16; off; off >>= 1) p += __shfl_xor_sync(0xFFFFFFFFu, p, off);
            if (lane == 0) {
                float xg = p + xb2v;
                int d = sdst[r];
                atomicAdd(&g_dx[(size_t)d * 3 + 0], srel[r][0] * xg);
                atomicAdd(&g_dx[(size_t)d * 3 + 1], srel[r][1] * xg);
                atomicAdd(&g_dx[(size_t)d * 3 + 2], srel[r][2] * xg);
            }
        }
    }
}

// ---------------------------------------------------------------------------
// Node (tf32 mma, static smem, R14 version — unchanged):
__global__ __launch_bounds__(256) void node_kernel(
    const float* __restrict__ h, const float* __restrict__ x,
    const float* __restrict__ nw1, const float* __restrict__ nb1,
    const float* __restrict__ nw2, const float* __restrict__ nb2,
    float* __restrict__ out)
{
    __shared__ float Ms[64][132];            // staging: tf32(y)
    __shared__ unsigned Bs[16][136];

    unsigned (*As)[20] = reinterpret_cast<unsigned(*)[20]>(&Ms[0][0]);

    const int tid  = threadIdx.x;
    const int w    = tid >> 5;
    const int lane = tid & 31;
    const int qd   = lane >> 2;
    const int l4   = lane & 3;
    const int R0   = (w >> 2) * 32;
    const int C0   = (w & 3) * 32;
    const int nbase = blockIdx.x * 64;

    float4 acc[2][4];
#pragma unroll
    for (int mt = 0; mt < 2; mt++)
#pragma unroll
        for (int nt = 0; nt < 4; nt++) acc[mt][nt] = make_float4(0.f, 0.f, 0.f, 0.f);

    float bregs[8];

    // ---------------- GEMM1: [mi|h](64x256) @ nw1(256x128) ----------------
    LOADBF(bregs, nw1, 0);

    for (int kt = 0; kt < 16; kt++) {
        const int k0 = kt * 16;
        __syncthreads();
        STOREBF(bregs);
#pragma unroll
        for (int l = 0; l < 4; l++) {
            int idx = tid + l * 256;
            int r = idx >> 4, c = idx & 15;
            int n = nbase + r, cg = k0 + c;
            float v = 0.0f;
            if (n < Nn) {
                if (cg < Hh) v = g_mi[(size_t)n * Hh + cg];
                else         v = h[(size_t)n * Hh + (cg - Hh)];
            }
            As[r][c] = f2tf(v);
        }
        if (kt < 15) { const int kn16 = (kt + 1) * 16; LOADBF(bregs, nw1, kn16); }
        __syncthreads();
#pragma unroll
        for (int ks = 0; ks < 16; ks += 8) {
            unsigned a[2][4], bfr[4][2];
#pragma unroll
            for (int mt = 0; mt < 2; mt++) {
                int r0 = R0 + mt * 16;
                a[mt][0] = As[r0 + qd][ks + l4];
                a[mt][1] = As[r0 + qd + 8][ks + l4];
                a[mt][2] = As[r0 + qd][ks + l4 + 4];
                a[mt][3] = As[r0 + qd + 8][ks + l4 + 4];
            }
#pragma unroll
            for (int nt = 0; nt < 4; nt++) {
                int c0 = C0 + nt * 8 + qd;
                bfr[nt][0] = Bs[ks + l4][c0];
                bfr[nt][1] = Bs[ks + l4 + 4][c0];
            }
#pragma unroll
            for (int mt = 0; mt < 2; mt++)
#pragma unroll
                for (int nt = 0; nt < 4; nt++)
                    mma_tf32(acc[mt][nt], a[mt][0], a[mt][1], a[mt][2], a[mt][3],
                             bfr[nt][0], bfr[nt][1]);
        }
    }

    // prologue for GEMM2's first B tile (overlaps epilogue 1)
    LOADBF(bregs, nw2, 0);
    __syncthreads();

    // Epilogue 1: y = relu(+nb1), store tf32 bits into Ms
#pragma unroll
    for (int nt = 0; nt < 4; nt++) {
        int c = C0 + nt * 8 + 2 * l4;
        float bx = nb1[c], by = nb1[c + 1];
#pragma unroll
        for (int mt = 0; mt < 2; mt++) {
            int rA = R0 + mt * 16 + qd;
            Ms[rA][c]     = __uint_as_float(f2tf(fmaxf(acc[mt][nt].x + bx, 0.f)));
            Ms[rA][c + 1] = __uint_as_float(f2tf(fmaxf(acc[mt][nt].y + by, 0.f)));
            Ms[rA + 8][c]     = __uint_as_float(f2tf(fmaxf(acc[mt][nt].z + bx, 0.f)));
            Ms[rA + 8][c + 1] = __uint_as_float(f2tf(fmaxf(acc[mt][nt].w + by, 0.f)));
        }
    }
    __syncthreads();

    // ---------------- GEMM2: y(64x128) @ nw2(128x128) ----------------
#pragma unroll
    for (int mt = 0; mt < 2; mt++)
#pragma unroll
        for (int nt = 0; nt < 4; nt++) acc[mt][nt] = make_float4(0.f, 0.f, 0.f, 0.f);

    for (int kt = 0; kt < 8; kt++) {
        const int k0 = kt * 16;
        __syncthreads();
        STOREBF(bregs);
        if (kt < 7) { const int kn16 = (kt + 1) * 16; LOADBF(bregs, nw2, kn16); }
        __syncthreads();
#pragma unroll
        for (int ks = 0; ks < 16; ks += 8) {
            unsigned a[2][4], bfr[4][2];
#pragma unroll
            for (int mt = 0; mt < 2; mt++) {
                int r0 = R0 + mt * 16;
                a[mt][0] = __float_as_uint(Ms[r0 + qd][k0 + ks + l4]);
                a[mt][1] = __float_as_uint(Ms[r0 + qd + 8][k0 + ks + l4]);
                a[mt][2] = __float_as_uint(Ms[r0 + qd][k0 + ks + l4 + 4]);
                a[mt][3] = __float_as_uint(Ms[r0 + qd + 8][k0 + ks + l4 + 4]);
            }
#pragma unroll
            for (int nt = 0; nt < 4; nt++) {
                int c0 = C0 + nt * 8 + qd;
                bfr[nt][0] = Bs[ks + l4][c0];
                bfr[nt][1] = Bs[ks + l4 + 4][c0];
            }
#pragma unroll
            for (int mt = 0; mt < 2; mt++)
#pragma unroll
                for (int nt = 0; nt < 4; nt++)
                    mma_tf32(acc[mt][nt], a[mt][0], a[mt][1], a[mt][2], a[mt][3],
                             bfr[nt][0], bfr[nt][1]);
        }
    }
    __syncthreads();

    // Epilogue 2: out = acc + nb2 (guarded direct stores)
#pragma unroll
    for (int nt = 0; nt < 4; nt++) {
        int c = C0 + nt * 8 + 2 * l4;
        float bx = nb2[c], by = nb2[c + 1];
#pragma unroll
        for (int mt = 0; mt < 2; mt++) {
            int r = R0 + mt * 16 + qd;
            int n = nbase + r;
            if (n < Nn) {
                out[(size_t)n * Hh + c]     = acc[mt][nt].x + bx;
                out[(size_t)n * Hh + c + 1] = acc[mt][nt].y + by;
            }
            int n2 = n + 8;
            if (n2 < Nn) {
                out[(size_t)n2 * Hh + c]     = acc[mt][nt].z + bx;
                out[(size_t)n2 * Hh + c + 1] = acc[mt][nt].w + by;
            }
        }
    }

    // x update: 64 nodes x 3 coords
    if (tid < 192) {
        int nl = tid / 3, c = tid % 3;
        int n = nbase + nl;
        if (n < Nn) {
            out[(size_t)Nn * Hh + (size_t)n * 3 + c] =
                x[(size_t)n * 3 + c] + g_dx[(size_t)n * 3 + c] * (1.0f / (float)Ee);
        }
    }
}

// ---------------------------------------------------------------------------
extern "C" void kernel_launch(void* const* d_in, const int* in_sizes, int n_in,
                              void* d_out, int out_size) {
    const float* h    = (const float*)d_in[0];
    const float* x    = (const float*)d_in[1];
    const float* ea   = (const float*)d_in[2];
    const float* ew1  = (const float*)d_in[3];
    const float* eb1  = (const float*)d_in[4];
    const float* ew2  = (const float*)d_in[5];
    const float* eb2  = (const float*)d_in[6];
    const float* infw = (const float*)d_in[7];
    const float* infb = (const float*)d_in[8];
    const float* nw1  = (const float*)d_in[9];
    const float* nb1  = (const float*)d_in[10];
    const float* nw2  = (const float*)d_in[11];
    const float* nb2  = (const float*)d_in[12];
    const float* xw1  = (const float*)d_in[13];
    const float* xb1  = (const float*)d_in[14];
    const float* xw2  = (const float*)d_in[15];
    const float* xb2  = (const float*)d_in[16];
    const int*   eidx = (const int*)d_in[17];
    float* out = (float*)d_out;

    zero_kernel<<<(Nn * Hh + 255) / 256, 256>>>();
    edge_kernel<<<Ee / 64, 256>>>(h, x, ea, ew1, eb1, ew2, eb2,
                                  infw, infb, xw1, xb1, xw2, xb2, eidx);
    node_kernel<<<(Nn + 63) / 64, 256>>>(h, x, nw1, nb1, nw2, nb2, out);
}

// round 16
// speedup vs baseline: 1.4078x; 1.0424x over previous
#include <cuda_runtime.h>
#include <math.h>
#include <stdint.h>

#define Nn 20000
#define Ee 320000
#define Hh 128
#define EFK 28     // edge_attr feature count (EF + K)
#define DIN 304    // 28 + 20 + 128 + 128

// Scratch (static device globals — no runtime allocation)
__device__ float g_mi[(size_t)Nn * Hh];   // segment_sum(mij*eij)
__device__ float g_dx[(size_t)Nn * 3];    // segment_sum(rel_x*xg)

// ---------------------------------------------------------------------------
__global__ __launch_bounds__(256) void zero_kernel() {
    int i = blockIdx.x * blockDim.x + threadIdx.x;
    if (i < Nn * Hh) g_mi[i] = 0.0f;
    if (i < Nn * 3)  g_dx[i] = 0.0f;
}

// ---------------------------------------------------------------------------
__device__ __forceinline__ unsigned f2tf(float f) {
    unsigned u;
    asm("cvt.rna.tf32.f32 %0, %1;" : "=r"(u) : "f"(f));
    return u;
}

__device__ __forceinline__ void mma_tf32(float4& d,
    unsigned a0, unsigned a1, unsigned a2, unsigned a3,
    unsigned b0, unsigned b1)
{
    asm volatile(
        "mma.sync.aligned.m16n8k8.row.col.f32.tf32.tf32.f32 "
        "{%0,%1,%2,%3}, {%4,%5,%6,%7}, {%8,%9}, {%0,%1,%2,%3};\n"
        : "+f"(d.x), "+f"(d.y), "+f"(d.z), "+f"(d.w)
        : "r"(a0), "r"(a1), "r"(a2), "r"(a3), "r"(b0), "r"(b1));
}

__device__ __forceinline__ void red_add_v4(float* addr, float4 v) {
    asm volatile("red.global.add.v4.f32 [%0], {%1,%2,%3,%4};"
                 :: "l"(addr), "f"(v.x), "f"(v.y), "f"(v.z), "f"(v.w)
                 : "memory");
}

// B-tile register prefetch: 16 rows x 128 cols, 8 floats/thread.
#define LOADBF(reg, wsrc, k0v)                                                  \
    { _Pragma("unroll")                                                         \
      for (int lb_ = 0; lb_ < 8; lb_++)                                         \
          (reg)[lb_] = (wsrc)[(size_t)((k0v) + (tid >> 7) + 2 * lb_) * Hh + (tid & 127)]; }

#define STOREBF(reg)                                                            \
    { _Pragma("unroll")                                                         \
      for (int lb_ = 0; lb_ < 8; lb_++)                                         \
          Bs[(tid >> 7) + 2 * lb_][tid & 127] = f2tf((reg)[lb_]); }

// ---------------------------------------------------------------------------
// Fused edge kernel (tf32 mma; A prefetch now covers ea tiles too;
// GEMM3 A-path reads raw tf32 bits written back during the eij loop)
__global__ __launch_bounds__(256) void edge_kernel(
    const float* __restrict__ h, const float* __restrict__ x,
    const float* __restrict__ ea,
    const float* __restrict__ w1, const float* __restrict__ b1,
    const float* __restrict__ w2, const float* __restrict__ b2,
    const float* __restrict__ infw, const float* __restrict__ infb,
    const float* __restrict__ xw1, const float* __restrict__ xb1,
    const float* __restrict__ xw2, const float* __restrict__ xb2,
    const int* __restrict__ eidx)
{
    __shared__ float Ms[64][132];            // staging: tf32(t1) -> mij(tf32 bits) -> u
    __shared__ unsigned Bs[16][136];         // B tile (tf32 bits), conflict-free pad
    __shared__ int   sdst[64];
    __shared__ float srel[64][3];
    __shared__ float sl2[64];

    // As aliases the front of Ms (only live inside GEMM1 k-loop)
    unsigned (*As)[20] = reinterpret_cast<unsigned(*)[20]>(&Ms[0][0]);

    const int tid  = threadIdx.x;
    const int w    = tid >> 5;          // warp 0..7
    const int lane = tid & 31;
    const int qd   = lane >> 2;         // 0..7
    const int l4   = lane & 3;          // 0..3
    const int wm   = w >> 2;            // 0..1  (M tile of 32)
    const int wn   = w & 3;             // 0..3  (N tile of 32)
    const int R0   = wm * 32;
    const int C0   = wn * 32;
    const int ebase = blockIdx.x * 64;

    if (tid < 64) {
        int e = ebase + tid;
        int d = eidx[e], s = eidx[Ee + e];
        sdst[tid] = d;
        float rx = x[d * 3 + 0] - x[s * 3 + 0];
        float ry = x[d * 3 + 1] - x[s * 3 + 1];
        float rz = x[d * 3 + 2] - x[s * 3 + 2];
        srel[tid][0] = rx; srel[tid][1] = ry; srel[tid][2] = rz;
        sl2[tid] = sqrtf(rx * rx + ry * ry + rz * rz);
    }
    __shared__ int ssrc[64];
    if (tid < 64) ssrc[tid] = eidx[Ee + ebase + tid];
    __syncthreads();

    float4 acc[2][4];
#pragma unroll
    for (int mt = 0; mt < 2; mt++)
#pragma unroll
        for (int nt = 0; nt < 4; nt++) acc[mt][nt] = make_float4(0.f, 0.f, 0.f, 0.f);

    const float delta = 100.0f / 19.0f;
    const float coeff = -0.5f / (delta * delta);

    float bregs[8];
    const int ar  = tid >> 2;                      // 0..63 (A row)
    const int ac4 = (tid & 3) * 4;                 // col group {0,4,8,12}

    // prefetch tile 0's A (all edge_attr; EFK*4=112B stride keeps 16B alignment)
    float4 ha = *(const float4*)&ea[(size_t)(ebase + ar) * EFK + ac4];

    // ---------------- GEMM1: feat(64x304) @ w1(304x128) ----------------
    LOADBF(bregs, w1, 0);

    for (int kt = 0; kt < 19; kt++) {
        __syncthreads();   // previous tile's frags consumed
        STOREBF(bregs);    // cvt + STS (data already in regs)
        if (kt == 1) {
            if (ac4 < 12) {
                As[ar][ac4 + 0] = f2tf(ha.x);
                As[ar][ac4 + 1] = f2tf(ha.y);
                As[ar][ac4 + 2] = f2tf(ha.z);
                As[ar][ac4 + 3] = f2tf(ha.w);
            } else {
                // local cols 12..15 = rbf j 0..3
#pragma unroll
                for (int jj = 0; jj < 4; jj++) {
                    float t = sl2[ar] - (float)jj * delta;
                    As[ar][12 + jj] = f2tf(expf(coeff * t * t));
                }
            }
        } else if (kt == 2) {
            // local cols ac4..ac4+3 = rbf j ac4+4 .. ac4+7
#pragma unroll
            for (int jj = 0; jj < 4; jj++) {
                float t = sl2[ar] - (float)(ac4 + 4 + jj) * delta;
                As[ar][ac4 + jj] = f2tf(expf(coeff * t * t));
            }
        } else {
            // tile 0 (ea) and tiles >=3 (h): prefetched float4
            As[ar][ac4 + 0] = f2tf(ha.x);
            As[ar][ac4 + 1] = f2tf(ha.y);
            As[ar][ac4 + 2] = f2tf(ha.z);
            As[ar][ac4 + 3] = f2tf(ha.w);
        }
        if (kt < 18) {
            const int kn = kt + 1;
            LOADBF(bregs, w1, kn * 16);
            if (kn == 1) {
                if (ac4 < 12)
                    ha = *(const float4*)&ea[(size_t)(ebase + ar) * EFK + 16 + ac4];
            } else if (kn >= 3) {
                const int* ridx = (kn < 11) ? sdst : ssrc;
                const int hb = ((kn - 3) & 7) * 16;
                ha = *(const float4*)&h[(size_t)ridx[ar] * Hh + hb + ac4];
            }
            // kn == 2: nothing to load (all rbf, computed in-window)
        }
        __syncthreads();
#pragma unroll
        for (int ks = 0; ks < 16; ks += 8) {
            unsigned a[2][4], bfr[4][2];
#pragma unroll
            for (int mt = 0; mt < 2; mt++) {
                int r0 = R0 + mt * 16;
                a[mt][0] = As[r0 + qd][ks + l4];
                a[mt][1] = As[r0 + qd + 8][ks + l4];
                a[mt][2] = As[r0 + qd][ks + l4 + 4];
                a[mt][3] = As[r0 + qd + 8][ks + l4 + 4];
            }
#pragma unroll
            for (int nt = 0; nt < 4; nt++) {
                int c0 = C0 + nt * 8 + qd;
                bfr[nt][0] = Bs[ks + l4][c0];
                bfr[nt][1] = Bs[ks + l4 + 4][c0];
            }
#pragma unroll
            for (int mt = 0; mt < 2; mt++)
#pragma unroll
                for (int nt = 0; nt < 4; nt++)
                    mma_tf32(acc[mt][nt], a[mt][0], a[mt][1], a[mt][2], a[mt][3],
                             bfr[nt][0], bfr[nt][1]);
        }
    }

    // prologue for GEMM2's first B tile (overlaps epilogue 1)
    LOADBF(bregs, w2, 0);
    __syncthreads();

    // Epilogue 1: relu(+b1), store tf32 into Ms
#pragma unroll
    for (int nt = 0; nt < 4; nt++) {
        int c = C0 + nt * 8 + 2 * l4;
        float bx = b1[c], by = b1[c + 1];
#pragma unroll
        for (int mt = 0; mt < 2; mt++) {
            int rA = R0 + mt * 16 + qd;
            Ms[rA][c]     = __uint_as_float(f2tf(fmaxf(acc[mt][nt].x + bx, 0.f)));
            Ms[rA][c + 1] = __uint_as_float(f2tf(fmaxf(acc[mt][nt].y + by, 0.f)));
            Ms[rA + 8][c]     = __uint_as_float(f2tf(fmaxf(acc[mt][nt].z + bx, 0.f)));
            Ms[rA + 8][c + 1] = __uint_as_float(f2tf(fmaxf(acc[mt][nt].w + by, 0.f)));
        }
    }
    __syncthreads();

    // ---------------- GEMM2: t1(64x128) @ w2(128x128) ----------------
#pragma unroll
    for (int mt = 0; mt < 2; mt++)
#pragma unroll
        for (int nt = 0; nt < 4; nt++) acc[mt][nt] = make_float4(0.f, 0.f, 0.f, 0.f);

    for (int kt = 0; kt < 8; kt++) {
        const int k0 = kt * 16;
        __syncthreads();
        STOREBF(bregs);
        if (kt < 7) { const int kn16 = (kt + 1) * 16; LOADBF(bregs, w2, kn16); }
        __syncthreads();
#pragma unroll
        for (int ks = 0; ks < 16; ks += 8) {
            unsigned a[2][4], bfr[4][2];
#pragma unroll
            for (int mt = 0; mt < 2; mt++) {
                int r0 = R0 + mt * 16;
                a[mt][0] = __float_as_uint(Ms[r0 + qd][k0 + ks + l4]);
                a[mt][1] = __float_as_uint(Ms[r0 + qd + 8][k0 + ks + l4]);
                a[mt][2] = __float_as_uint(Ms[r0 + qd][k0 + ks + l4 + 4]);
                a[mt][3] = __float_as_uint(Ms[r0 + qd + 8][k0 + ks + l4 + 4]);
            }
#pragma unroll
            for (int nt = 0; nt < 4; nt++) {
                int c0 = C0 + nt * 8 + qd;
                bfr[nt][0] = Bs[ks + l4][c0];
                bfr[nt][1] = Bs[ks + l4 + 4][c0];
            }
#pragma unroll
            for (int mt = 0; mt < 2; mt++)
#pragma unroll
                for (int nt = 0; nt < 4; nt++)
                    mma_tf32(acc[mt][nt], a[mt][0], a[mt][1], a[mt][2], a[mt][3],
                             bfr[nt][0], bfr[nt][1]);
        }
    }

    // prologue for GEMM3's first B tile (overlaps epilogue 2 + eij/atomics)
    LOADBF(bregs, xw1, 0);
    __syncthreads();   // all Ms reads done before overwrite

    // Epilogue 2: mij = relu(+b2), store fp32 into Ms
#pragma unroll
    for (int nt = 0; nt < 4; nt++) {
        int c = C0 + nt * 8 + 2 * l4;
        float bx = b2[c], by = b2[c + 1];
#pragma unroll
        for (int mt = 0; mt < 2; mt++) {
            int rA = R0 + mt * 16 + qd;
            Ms[rA][c]     = fmaxf(acc[mt][nt].x + bx, 0.f);
            Ms[rA][c + 1] = fmaxf(acc[mt][nt].y + by, 0.f);
            Ms[rA + 8][c]     = fmaxf(acc[mt][nt].z + bx, 0.f);
            Ms[rA + 8][c + 1] = fmaxf(acc[mt][nt].w + by, 0.f);
        }
    }
    __syncthreads();

    // eij + mi atomics; convert mij rows to tf32 bits in-place for GEMM3
    {
        float4 iw4 = *(const float4*)&infw[lane * 4];
        float ib = infb[0];
#pragma unroll
        for (int i = 0; i < 8; i++) {
            int r = w * 8 + i;
            float4 mv = *(const float4*)&Ms[r][lane * 4];
            float p = mv.x * iw4.x + mv.y * iw4.y + mv.z * iw4.z + mv.w * iw4.w;
#pragma unroll
            for (int off = 16; off; off >>= 1) p += __shfl_xor_sync(0xFFFFFFFFu, p, off);
            float eij = 1.0f / (1.0f + expf(-(p + ib)));
            int d = sdst[r];
            red_add_v4(&g_mi[(size_t)d * Hh + lane * 4],
                       make_float4(mv.x * eij, mv.y * eij, mv.z * eij, mv.w * eij));
            *(uint4*)&Ms[r][lane * 4] =
                make_uint4(f2tf(mv.x), f2tf(mv.y), f2tf(mv.z), f2tf(mv.w));
        }
    }
    __syncthreads();

    // ---------------- GEMM3: mij(64x128) @ xw1(128x128) ----------------
#pragma unroll
    for (int mt = 0; mt < 2; mt++)
#pragma unroll
        for (int nt = 0; nt < 4; nt++) acc[mt][nt] = make_float4(0.f, 0.f, 0.f, 0.f);

    for (int kt = 0; kt < 8; kt++) {
        const int k0 = kt * 16;
        __syncthreads();
        STOREBF(bregs);
        if (kt < 7) { const int kn16 = (kt + 1) * 16; LOADBF(bregs, xw1, kn16); }
        __syncthreads();
#pragma unroll
        for (int ks = 0; ks < 16; ks += 8) {
            unsigned a[2][4], bfr[4][2];
#pragma unroll
            for (int mt = 0; mt < 2; mt++) {
                int r0 = R0 + mt * 16;
                a[mt][0] = __float_as_uint(Ms[r0 + qd][k0 + ks + l4]);
                a[mt][1] = __float_as_uint(Ms[r0 + qd + 8][k0 + ks + l4]);
                a[mt][2] = __float_as_uint(Ms[r0 + qd][k0 + ks + l4 + 4]);
                a[mt][3] = __float_as_uint(Ms[r0 + qd + 8][k0 + ks + l4 + 4]);
            }
#pragma unroll
            for (int nt = 0; nt < 4; nt++) {
                int c0 = C0 + nt * 8 + qd;
                bfr[nt][0] = Bs[ks + l4][c0];
                bfr[nt][1] = Bs[ks + l4 + 4][c0];
            }
#pragma unroll
            for (int mt = 0; mt < 2; mt++)
#pragma unroll
                for (int nt = 0; nt < 4; nt++)
                    mma_tf32(acc[mt][nt], a[mt][0], a[mt][1], a[mt][2], a[mt][3],
                             bfr[nt][0], bfr[nt][1]);
        }
    }
    __syncthreads();

    // Epilogue 3: u = relu(+xb1), store into Ms
#pragma unroll
    for (int nt = 0; nt < 4; nt++) {
        int c = C0 + nt * 8 + 2 * l4;
        float bx = xb1[c], by = xb1[c + 1];
#pragma unroll
        for (int mt = 0; mt < 2; mt++) {
            int rA = R0 + mt * 16 + qd;
            Ms[rA][c]     = fmaxf(acc[mt][nt].x + bx, 0.f);
            Ms[rA][c + 1] = fmaxf(acc[mt][nt].y + by, 0.f);
            Ms[rA + 8][c]     = fmaxf(acc[mt][nt].z + bx, 0.f);
            Ms[rA + 8][c + 1] = fmaxf(acc[mt][nt].w + by, 0.f);
        }
    }
    __syncthreads();

    // xg + dx atomics
    {
        float4 xw4 = *(const float4*)&xw2[lane * 4];
        float xb2v = xb2[0];
#pragma unroll
        for (int i = 0; i < 8; i++) {
            int r = w * 8 + i;
            float4 uv = *(const float4*)&Ms[r][lane * 4];
            float p = uv.x * xw4.x + uv.y * xw4.y + uv.z * xw4.z + uv.w * xw4.w;
#pragma unroll
            for (int off = 16; off; off >>= 1) p += __shfl_xor_sync(0xFFFFFFFFu, p, off);
            if (lane == 0) {
                float xg = p + xb2v;
                int d = sdst[r];
                atomicAdd(&g_dx[(size_t)d * 3 + 0], srel[r][0] * xg);
                atomicAdd(&g_dx[(size_t)d * 3 + 1], srel[r][1] * xg);
                atomicAdd(&g_dx[(size_t)d * 3 + 2], srel[r][2] * xg);
            }
        }
    }
}

// ---------------------------------------------------------------------------
// Node (tf32 mma, static smem, + A-side prefetch):
__global__ __launch_bounds__(256) void node_kernel(
    const float* __restrict__ h, const float* __restrict__ x,
    const float* __restrict__ nw1, const float* __restrict__ nb1,
    const float* __restrict__ nw2, const float* __restrict__ nb2,
    float* __restrict__ out)
{
    __shared__ float Ms[64][132];            // staging: tf32(y)
    __shared__ unsigned Bs[16][136];

    unsigned (*As)[20] = reinterpret_cast<unsigned(*)[20]>(&Ms[0][0]);

    const int tid  = threadIdx.x;
    const int w    = tid >> 5;
    const int lane = tid & 31;
    const int qd   = lane >> 2;
    const int l4   = lane & 3;
    const int R0   = (w >> 2) * 32;
    const int C0   = (w & 3) * 32;
    const int nbase = blockIdx.x * 64;

    const int ar  = tid >> 2;
    const int ac4 = (tid & 3) * 4;
    const int an  = nbase + ar;

    float4 acc[2][4];
#pragma unroll
    for (int mt = 0; mt < 2; mt++)
#pragma unroll
        for (int nt = 0; nt < 4; nt++) acc[mt][nt] = make_float4(0.f, 0.f, 0.f, 0.f);

    float bregs[8];
    float4 na = make_float4(0.f, 0.f, 0.f, 0.f);
    if (an < Nn) na = *(const float4*)&g_mi[(size_t)an * Hh + ac4];

    // ---------------- GEMM1: [mi|h](64x256) @ nw1(256x128) ----------------
    LOADBF(bregs, nw1, 0);

    for (int kt = 0; kt < 16; kt++) {
        __syncthreads();
        STOREBF(bregs);
        As[ar][ac4 + 0] = f2tf(na.x);
        As[ar][ac4 + 1] = f2tf(na.y);
        As[ar][ac4 + 2] = f2tf(na.z);
        As[ar][ac4 + 3] = f2tf(na.w);
        if (kt < 15) {
            const int kn = kt + 1;
            LOADBF(bregs, nw1, kn * 16);
            na = make_float4(0.f, 0.f, 0.f, 0.f);
            if (an < Nn) {
                if (kn < 8) na = *(const float4*)&g_mi[(size_t)an * Hh + kn * 16 + ac4];
                else        na = *(const float4*)&h[(size_t)an * Hh + (kn - 8) * 16 + ac4];
            }
        }
        __syncthreads();
#pragma unroll
        for (int ks = 0; ks < 16; ks += 8) {
            unsigned a[2][4], bfr[4][2];
#pragma unroll
            for (int mt = 0; mt < 2; mt++) {
                int r0 = R0 + mt * 16;
                a[mt][0] = As[r0 + qd][ks + l4];
                a[mt][1] = As[r0 + qd + 8][ks + l4];
                a[mt][2] = As[r0 + qd][ks + l4 + 4];
                a[mt][3] = As[r0 + qd + 8][ks + l4 + 4];
            }
#pragma unroll
            for (int nt = 0; nt < 4; nt++) {
                int c0 = C0 + nt * 8 + qd;
                bfr[nt][0] = Bs[ks + l4][c0];
                bfr[nt][1] = Bs[ks + l4 + 4][c0];
            }
#pragma unroll
            for (int mt = 0; mt < 2; mt++)
#pragma unroll
                for (int nt = 0; nt < 4; nt++)
                    mma_tf32(acc[mt][nt], a[mt][0], a[mt][1], a[mt][2], a[mt][3],
                             bfr[nt][0], bfr[nt][1]);
        }
    }

    // prologue for GEMM2's first B tile (overlaps epilogue 1)
    LOADBF(bregs, nw2, 0);
    __syncthreads();

    // Epilogue 1: y = relu(+nb1), store tf32 bits into Ms
#pragma unroll
    for (int nt = 0; nt < 4; nt++) {
        int c = C0 + nt * 8 + 2 * l4;
        float bx = nb1[c], by = nb1[c + 1];
#pragma unroll
        for (int mt = 0; mt < 2; mt++) {
            int rA = R0 + mt * 16 + qd;
            Ms[rA][c]     = __uint_as_float(f2tf(fmaxf(acc[mt][nt].x + bx, 0.f)));
            Ms[rA][c + 1] = __uint_as_float(f2tf(fmaxf(acc[mt][nt].y + by, 0.f)));
            Ms[rA + 8][c]     = __uint_as_float(f2tf(fmaxf(acc[mt][nt].z + bx, 0.f)));
            Ms[rA + 8][c + 1] = __uint_as_float(f2tf(fmaxf(acc[mt][nt].w + by, 0.f)));
        }
    }
    __syncthreads();

    // ---------------- GEMM2: y(64x128) @ nw2(128x128) ----------------
#pragma unroll
    for (int mt = 0; mt < 2; mt++)
#pragma unroll
        for (int nt = 0; nt < 4; nt++) acc[mt][nt] = make_float4(0.f, 0.f, 0.f, 0.f);

    for (int kt = 0; kt < 8; kt++) {
        const int k0 = kt * 16;
        __syncthreads();
        STOREBF(bregs);
        if (kt < 7) { const int kn16 = (kt + 1) * 16; LOADBF(bregs, nw2, kn16); }
        __syncthreads();
#pragma unroll
        for (int ks = 0; ks < 16; ks += 8) {
            unsigned a[2][4], bfr[4][2];
#pragma unroll
            for (int mt = 0; mt < 2; mt++) {
                int r0 = R0 + mt * 16;
                a[mt][0] = __float_as_uint(Ms[r0 + qd][k0 + ks + l4]);
                a[mt][1] = __float_as_uint(Ms[r0 + qd + 8][k0 + ks + l4]);
                a[mt][2] = __float_as_uint(Ms[r0 + qd][k0 + ks + l4 + 4]);
                a[mt][3] = __float_as_uint(Ms[r0 + qd + 8][k0 + ks + l4 + 4]);
            }
#pragma unroll
            for (int nt = 0; nt < 4; nt++) {
                int c0 = C0 + nt * 8 + qd;
                bfr[nt][0] = Bs[ks + l4][c0];
                bfr[nt][1] = Bs[ks + l4 + 4][c0];
            }
#pragma unroll
            for (int mt = 0; mt < 2; mt++)
#pragma unroll
                for (int nt = 0; nt < 4; nt++)
                    mma_tf32(acc[mt][nt], a[mt][0], a[mt][1], a[mt][2], a[mt][3],
                             bfr[nt][0], bfr[nt][1]);
        }
    }
    __syncthreads();

    // Epilogue 2: out = acc + nb2 (guarded direct stores)
#pragma unroll
    for (int nt = 0; nt < 4; nt++) {
        int c = C0 + nt * 8 + 2 * l4;
        float bx = nb2[c], by = nb2[c + 1];
#pragma unroll
        for (int mt = 0; mt < 2; mt++) {
            int r = R0 + mt * 16 + qd;
            int n = nbase + r;
            if (n < Nn) {
                out[(size_t)n * Hh + c]     = acc[mt][nt].x + bx;
                out[(size_t)n * Hh + c + 1] = acc[mt][nt].y + by;
            }
            int n2 = n + 8;
            if (n2 < Nn) {
                out[(size_t)n2 * Hh + c]     = acc[mt][nt].z + bx;
                out[(size_t)n2 * Hh + c + 1] = acc[mt][nt].w + by;
            }
        }
    }

    // x update: 64 nodes x 3 coords
    if (tid < 192) {
        int nl = tid / 3, c = tid % 3;
        int n = nbase + nl;
        if (n < Nn) {
            out[(size_t)Nn * Hh + (size_t)n * 3 + c] =
                x[(size_t)n * 3 + c] + g_dx[(size_t)n * 3 + c] * (1.0f / (float)Ee);
        }
    }
}

// ---------------------------------------------------------------------------
extern "C" void kernel_launch(void* const* d_in, const int* in_sizes, int n_in,
                              void* d_out, int out_size) {
    const float* h    = (const float*)d_in[0];
    const float* x    = (const float*)d_in[1];
    const float* ea   = (const float*)d_in[2];
    const float* ew1  = (const float*)d_in[3];
    const float* eb1  = (const float*)d_in[4];
    const float* ew2  = (const float*)d_in[5];
    const float* eb2  = (const float*)d_in[6];
    const float* infw = (const float*)d_in[7];
    const float* infb = (const float*)d_in[8];
    const float* nw1  = (const float*)d_in[9];
    const float* nb1  = (const float*)d_in[10];
    const float* nw2  = (const float*)d_in[11];
    const float* nb2  = (const float*)d_in[12];
    const float* xw1  = (const float*)d_in[13];
    const float* xb1  = (const float*)d_in[14];
    const float* xw2  = (const float*)d_in[15];
    const float* xb2  = (const float*)d_in[16];
    const int*   eidx = (const int*)d_in[17];
    float* out = (float*)d_out;

    zero_kernel<<<(Nn * Hh + 255) / 256, 256>>>();
    edge_kernel<<<Ee / 64, 256>>>(h, x, ea, ew1, eb1, ew2, eb2,
                                  infw, infb, xw1, xb1, xw2, xb2, eidx);
    node_kernel<<<(Nn + 63) / 64, 256>>>(h, x, nw1, nb1, nw2, nb2, out);
}